// round 4
// baseline (speedup 1.0000x reference)
#include <cuda_runtime.h>
#include <math.h>

// ---------------- problem constants ----------------
#define BSZ 512
#define DD 100
#define TOTAL_P 1086
#define NTH 256

// scratch buffer offsets (floats) — only L0 outputs needed now
#define SCH1_L0 0ull            // [2][512*124][100]
#define SCH0_L0 12697600ull     // [2][512*4][100]
#define RAND_L0 13107200ull     // [512*4][100]
#define SCRATCH_TOTAL 13312000ull

__device__ float g_buf[SCRATCH_TOTAL];

typedef unsigned long long ull;

__device__ __forceinline__ ull fma2(ull a, ull b, ull c) {
    ull d;
    asm("fma.rn.f32x2 %0, %1, %2, %3;" : "=l"(d) : "l"(a), "l"(b), "l"(c));
    return d;
}
__device__ __forceinline__ ull pack2(float a) {
    ull d;
    asm("mov.b64 %0, {%1, %1};" : "=l"(d) : "f"(a));
    return d;
}
__device__ __forceinline__ void unpack2(ull v, float& lo, float& hi) {
    asm("mov.b64 {%0, %1}, %2;" : "=f"(lo), "=f"(hi) : "l"(v));
}

// ================= level-0 kernel (unchanged, 1 launch, 3 jobs) =================
struct Job {
    const float* gsrc;
    float*       out;
    const float* Ws;
    const float* Wn;
    const int*   neigh;
    int mode;              // 1 = type_embed, 2 = rw_embed
    int idx;
    int nseg;
    int s[5];
    int fan[4];
    int noff[5];
    int nb_b, nb_t;
    int Rout;
    int Rin;
    int rows;
    int blk0;
};
struct MultiParams {
    Job job[3];
    int njobs;
    const int* nodeids;
};

#define SM_AS   0
#define SM_AM   6400
#define SM_W    12800
#define SM_SELF 22800
#define SM_FAN  22864
#define SM_COFF 22928
#define SM_INVF 23504
#define SM_FLOATS 23568
#define AGG_SMEM_BYTES (SM_FLOATS * 4)

__global__ __launch_bounds__(160) void agg_multi_kernel(MultiParams p) {
    extern __shared__ float sm[];
    float* sAs  = sm + SM_AS;
    float* sAm  = sm + SM_AM;
    float* sW   = sm + SM_W;
    int*   sSelf = (int*)(sm + SM_SELF);
    int*   sFan  = (int*)(sm + SM_FAN);
    int*   sCoff = (int*)(sm + SM_COFF);
    float* sInvF = sm + SM_INVF;

    const int tid = threadIdx.x;

    int j = 0;
    if (p.njobs > 1 && (int)blockIdx.x >= p.job[1].blk0) j = 1;
    if (p.njobs > 2 && (int)blockIdx.x >= p.job[2].blk0) j = 2;
    Job jb = p.job[j];
    const int R0 = (blockIdx.x - jb.blk0) * 64;

    {
        const float* Ws = jb.Ws;
        const float* Wn = jb.Wn;
        for (int e = tid; e < 5000; e += 160) {
            int k = e / 50, pr = e - k * 50;
            int c = pr * 2;
            float2 v;
            if (c < 50) v = *(const float2*)(Ws + k * 50 + c);
            else        v = *(const float2*)(Wn + k * 50 + (c - 50));
            *(float2*)&sW[k * 100 + c] = v;
        }
    }

    if (tid < 64) {
        int R = R0 + tid;
        if (R >= jb.rows) R = jb.rows - 1;
        int t = (R >= jb.Rout) ? 1 : 0;
        int g = R - t * jb.Rout;
        int kk = 0, off = 0;
        while (kk + 1 < jb.nseg && g >= off + BSZ * jb.s[kk]) { off += BSZ * jb.s[kk]; kk++; }
        int local = g - off;
        int b = local / jb.s[kk];
        int i = local - b * jb.s[kk];
        int fan = jb.fan[kk];
        sFan[tid]  = fan;
        sInvF[tid] = 1.0f / (float)fan;
        int soff;
        {
            int id = (kk == 0) ? p.nodeids[b]
                               : jb.neigh[b * jb.nb_b + t * jb.nb_t + jb.noff[kk] + i];
            soff = (jb.mode == 1) ? (id * 400 + t * 200 + jb.idx * 100) : id * DD;
        }
        sSelf[tid] = soff;
        {
            int nb2 = b * jb.nb_b + t * jb.nb_t + jb.noff[kk + 1] + i * fan;
            for (int jj = 0; jj < fan; jj++) {
                int id = jb.neigh[nb2 + jj];
                sCoff[tid * 9 + jj] = (jb.mode == 1) ? (id * 400 + t * 200 + jb.idx * 100)
                                                     : id * DD;
            }
        }
    }
    __syncthreads();

    const float* src = jb.gsrc;
    for (int e = tid; e < 1600; e += 160) {
        int row = e / 25, k4 = e - row * 25;
        float4 v = *(const float4*)(src + sSelf[row] + k4 * 4);
        int kb = k4 * 4;
        sAs[(kb + 0) * 64 + row] = v.x;
        sAs[(kb + 1) * 64 + row] = v.y;
        sAs[(kb + 2) * 64 + row] = v.z;
        sAs[(kb + 3) * 64 + row] = v.w;
    }
    for (int e = tid; e < 1600; e += 160) {
        int row = e / 25, k4 = e - row * 25;
        int f = sFan[row];
        const int* co = sCoff + row * 9;
        float x = 0.f, y = 0.f, z = 0.f, w = 0.f;
#pragma unroll
        for (int jj = 0; jj < 9; jj++) {
            if (jj < f) {
                float4 v = *(const float4*)(src + co[jj] + k4 * 4);
                x += v.x; y += v.y; z += v.z; w += v.w;
            }
        }
        float iv = sInvF[row];
        int kb = k4 * 4;
        sAm[(kb + 0) * 64 + row] = x * iv;
        sAm[(kb + 1) * 64 + row] = y * iv;
        sAm[(kb + 2) * 64 + row] = z * iv;
        sAm[(kb + 3) * 64 + row] = w * iv;
    }
    __syncthreads();

    const int ct = tid % 10, rt = tid / 10;
    const int c0 = ct * 10, r0 = rt * 4;
    const float* Ab = (ct < 5) ? sAs : sAm;

    ull acc[4][5];
#pragma unroll
    for (int r = 0; r < 4; r++)
#pragma unroll
        for (int q = 0; q < 5; q++) acc[r][q] = 0ull;

#pragma unroll 2
    for (int k = 0; k < 100; k++) {
        const float* ap = Ab + k * 64 + r0;
        ull a0 = pack2(ap[0]);
        ull a1 = pack2(ap[1]);
        ull a2 = pack2(ap[2]);
        ull a3 = pack2(ap[3]);
        const ull* wp = (const ull*)&sW[k * 100 + c0];
        ull w0 = wp[0], w1 = wp[1], w2 = wp[2], w3 = wp[3], w4 = wp[4];
        acc[0][0] = fma2(a0, w0, acc[0][0]); acc[0][1] = fma2(a0, w1, acc[0][1]);
        acc[0][2] = fma2(a0, w2, acc[0][2]); acc[0][3] = fma2(a0, w3, acc[0][3]);
        acc[0][4] = fma2(a0, w4, acc[0][4]);
        acc[1][0] = fma2(a1, w0, acc[1][0]); acc[1][1] = fma2(a1, w1, acc[1][1]);
        acc[1][2] = fma2(a1, w2, acc[1][2]); acc[1][3] = fma2(a1, w3, acc[1][3]);
        acc[1][4] = fma2(a1, w4, acc[1][4]);
        acc[2][0] = fma2(a2, w0, acc[2][0]); acc[2][1] = fma2(a2, w1, acc[2][1]);
        acc[2][2] = fma2(a2, w2, acc[2][2]); acc[2][3] = fma2(a2, w3, acc[2][3]);
        acc[2][4] = fma2(a2, w4, acc[2][4]);
        acc[3][0] = fma2(a3, w0, acc[3][0]); acc[3][1] = fma2(a3, w1, acc[3][1]);
        acc[3][2] = fma2(a3, w2, acc[3][2]); acc[3][3] = fma2(a3, w3, acc[3][3]);
        acc[3][4] = fma2(a3, w4, acc[3][4]);
    }

#pragma unroll
    for (int r = 0; r < 4; r++) {
        int R = R0 + r0 + r;
        if (R < jb.rows) {
            int t = (R >= jb.Rout) ? 1 : 0;
            int g = R - t * jb.Rout;
            float* op = jb.out + (size_t)(t * jb.Rout + g) * DD + c0;
#pragma unroll
            for (int q = 0; q < 5; q++) {
                float lo, hi;
                unpack2(acc[r][q], lo, hi);
                float2 o;
                o.x = fmaxf(lo, 0.f);
                o.y = fmaxf(hi, 0.f);
                *(float2*)(op + 2 * q) = o;
            }
        }
    }
}

// ================= fused tail kernel: levels 1+ for all pipelines + attention =================
// One block per batch element b. smem regions:
//   FA [12400]  big feats buffer (also attn scratch)
//   FB [1900]   small feats buffer (also attn misc)
//   M  [1900]   mean scratch
//   W  [10000]  weight staging [k][100] = [Ws | Wn]
//   SPEC [600]  X rows (v*2+t)
#define TK_FA   0
#define TK_FB   12400
#define TK_M    14300
#define TK_W    16200
#define TK_SPEC 26200
#define TK_FLOATS 26800
#define TK_SMEM_BYTES (TK_FLOATS * 4)

__device__ __forceinline__ void load_W(float* W, const float* Ws, const float* Wn, int tid) {
    for (int e = tid; e < 5000; e += NTH) {
        int k = e / 50, c2 = (e - k * 50) * 2;
        float2 v;
        if (c2 < 50) v = *(const float2*)(Ws + k * 50 + c2);
        else         v = *(const float2*)(Wn + k * 50 + (c2 - 50));
        *(float2*)&W[k * 100 + c2] = v;
    }
}

// generic aggregation level: IN (rows per in-list), OUT (nout rows), mean scratch M.
// O1,O2,O3 = in-list segment start offsets (cumsum of sizes); F0..F2 = fans.
__device__ __forceinline__ void do_level(
    const float* IN, float* OUT, float* M, const float* W,
    int nout, int O1, int O2, int O3, int F0, int F1, int F2, int tid)
{
    for (int it = tid; it < nout * 25; it += NTH) {
        int j = it / 25, k4 = (it - (it / 25) * 25) * 4;
        int k = (j >= O2) ? 2 : ((j >= O1) ? 1 : 0);
        int f  = (k == 0) ? F0 : (k == 1 ? F1 : F2);
        int o  = (k == 0) ? 0  : (k == 1 ? O1 : O2);
        int cs = (k == 0) ? O1 : (k == 1 ? O2 : O3);
        int cb = cs + (j - o) * f;
        float x = 0.f, y = 0.f, z = 0.f, w = 0.f;
        for (int i = 0; i < f; i++) {
            float4 v = *(const float4*)&IN[(cb + i) * 100 + k4];
            x += v.x; y += v.y; z += v.z; w += v.w;
        }
        float iv = 1.0f / (float)f;
        float4 r; r.x = x * iv; r.y = y * iv; r.z = z * iv; r.w = w * iv;
        *(float4*)&M[j * 100 + k4] = r;
    }
    __syncthreads();
    for (int it = tid; it < nout * 50; it += NTH) {
        int j = it / 50, cc = it - (it / 50) * 50;
        int h = cc / 25, c2 = cc - h * 25;
        int col = h * 50 + c2 * 2;
        const float* A = h ? (M + j * 100) : (IN + j * 100);
        ull acc = 0ull;
#pragma unroll 4
        for (int k = 0; k < 100; k++) {
            ull wv = *(const ull*)&W[k * 100 + col];
            acc = fma2(pack2(A[k]), wv, acc);
        }
        float lo, hi; unpack2(acc, lo, hi);
        OUT[j * 100 + col]     = fmaxf(lo, 0.f);
        OUT[j * 100 + col + 1] = fmaxf(hi, 0.f);
    }
    __syncthreads();
}

__device__ __forceinline__ void mha_stage(
    float* X, float* LNX, float* Q, float* K, float* V, float* O,
    float* mu, float* rs, float* SC, float* ATT,
    int nb, int na,
    const float* __restrict__ Wq, const float* __restrict__ Wk,
    const float* __restrict__ Wv, const float* __restrict__ Wf,
    const float* __restrict__ gam, const float* __restrict__ bet, int tid)
{
    if (tid < 6) {
        float s = 0.f;
        for (int d = 0; d < 100; d++) s += X[tid * 100 + d];
        float m = s * 0.01f;
        float v = 0.f;
        for (int d = 0; d < 100; d++) { float z = X[tid * 100 + d] - m; v += z * z; }
        mu[tid] = m;
        rs[tid] = rsqrtf(v * 0.01f + 1e-6f);
    }
    __syncthreads();
    for (int e = tid; e < 600; e += NTH) {
        int r = e / 100, d = e - r * 100;
        LNX[e] = (X[e] - mu[r]) * rs[r] * gam[d] + bet[d];
    }
    __syncthreads();
    if (tid < 100) {
        float aq[6], ak[6], av[6];
#pragma unroll
        for (int r = 0; r < 6; r++) { aq[r] = 0.f; ak[r] = 0.f; av[r] = 0.f; }
        for (int k2 = 0; k2 < 100; k2++) {
            float wq = Wq[k2 * 100 + tid];
            float wk = Wk[k2 * 100 + tid];
            float wv = Wv[k2 * 100 + tid];
#pragma unroll
            for (int r = 0; r < 6; r++) {
                aq[r] += LNX[r * 100 + k2] * wq;
                ak[r] += X[r * 100 + k2] * wk;
                av[r] += X[r * 100 + k2] * wv;
            }
        }
#pragma unroll
        for (int r = 0; r < 6; r++) {
            Q[r * 100 + tid] = aq[r];
            K[r * 100 + tid] = ak[r];
            V[r * 100 + tid] = av[r];
        }
    }
    __syncthreads();
    int nsc = nb * na * na;
    if (tid < nsc) {
        int bi = tid / (na * na), rem = tid - bi * na * na;
        int qa = rem / na, ka = rem - qa * na;
        const float* qp = Q + (bi * na + qa) * 100;
        const float* kp = K + (bi * na + ka) * 100;
        float s = 0.f;
        for (int d = 0; d < 100; d++) s += qp[d] * kp[d];
        SC[tid] = s * 0.1f;
    }
    __syncthreads();
    if (tid < nb * na) {
        int base = tid * na;
        float mx = -1e30f;
        for (int ka = 0; ka < na; ka++) mx = fmaxf(mx, SC[base + ka]);
        float ev[3], sum = 0.f;
        for (int ka = 0; ka < na; ka++) { ev[ka] = expf(SC[base + ka] - mx); sum += ev[ka]; }
        float inv = 1.0f / sum;
        for (int ka = 0; ka < na; ka++) ATT[base + ka] = ev[ka] * inv;
    }
    __syncthreads();
    if (tid < 100) {
        for (int bi = 0; bi < nb; bi++)
            for (int qa = 0; qa < na; qa++) {
                float acc = 0.f;
                for (int ka = 0; ka < na; ka++)
                    acc += ATT[(bi * na + qa) * na + ka] * V[(bi * na + ka) * 100 + tid];
                O[(bi * na + qa) * 100 + tid] = acc;
            }
    }
    __syncthreads();
    if (tid < 100) {
        float acc[6];
#pragma unroll
        for (int r = 0; r < 6; r++) acc[r] = 0.f;
        for (int k2 = 0; k2 < 100; k2++) {
            float wf = Wf[k2 * 100 + tid];
#pragma unroll
            for (int r = 0; r < 6; r++) acc[r] += O[r * 100 + k2] * wf;
        }
#pragma unroll
        for (int r = 0; r < 6; r++) X[r * 100 + tid] = acc[r] + X[r * 100 + tid];
    }
    __syncthreads();
}

__global__ __launch_bounds__(NTH) void tail_kernel(
    const float* __restrict__ sch1_l0, const float* __restrict__ sch0_l0,
    const float* __restrict__ rand_l0,
    const float* __restrict__ agg1_self, const float* __restrict__ agg1_neigh,
    const float* __restrict__ agg0_self, const float* __restrict__ agg0_neigh,
    const float* __restrict__ rand_self, const float* __restrict__ rand_neigh,
    const int* __restrict__ edgetype, const int* __restrict__ nodeids,
    const float* __restrict__ base_embed, const float* __restrict__ reflect,
    const float* __restrict__ vWq, const float* __restrict__ vWk,
    const float* __restrict__ vWv, const float* __restrict__ vWf,
    const float* __restrict__ vg, const float* __restrict__ vb,
    const float* __restrict__ mWq, const float* __restrict__ mWk,
    const float* __restrict__ mWv, const float* __restrict__ mWf,
    const float* __restrict__ mg, const float* __restrict__ mb,
    float* __restrict__ outp)
{
    extern __shared__ float sm[];
    float* FA   = sm + TK_FA;
    float* FB   = sm + TK_FB;
    float* M    = sm + TK_M;
    float* W    = sm + TK_W;
    float* SPEC = sm + TK_SPEC;

    const int b = blockIdx.x;
    const int tid = threadIdx.x;

    // ---------- per-type schema pipelines ----------
    for (int t = 0; t < 2; t++) {
        // schema1: load 124 L0 rows for (b,t)
        const float* L0 = sch1_l0 + (size_t)t * (512 * 124) * 100;
        for (int e = tid; e < 124 * 25; e += NTH) {
            int row = e / 25, k4 = (e - (e / 25) * 25) * 4;
            int g;
            if (row == 0)      g = b;
            else if (row < 4)  g = 512 + b * 3 + (row - 1);
            else if (row < 19) g = 2048 + b * 15 + (row - 4);
            else               g = 9728 + b * 105 + (row - 19);
            *(float4*)&FA[row * 100 + k4] = *(const float4*)&L0[(size_t)g * 100 + k4];
        }
        load_W(W, agg1_self + 5000, agg1_neigh + 5000, tid);
        __syncthreads();
        do_level(FA, FB, M, W, 19, 1, 4, 19, 3, 5, 7, tid);      // L1: 124 -> 19
        load_W(W, agg1_self + 10000, agg1_neigh + 10000, tid);
        __syncthreads();
        do_level(FB, FA, M, W, 4, 1, 4, 999, 3, 5, 0, tid);      // L2: 19 -> 4
        load_W(W, agg1_self + 15000, agg1_neigh + 15000, tid);
        __syncthreads();
        do_level(FA, SPEC + (2 + t) * 100, M, W, 1, 1, 999, 999, 3, 0, 0, tid); // L3 -> v1

        // schema0: 4 L0 rows
        const float* S0 = sch0_l0 + (size_t)t * (512 * 4) * 100;
        for (int e = tid; e < 4 * 25; e += NTH) {
            int row = e / 25, k4 = (e - (e / 25) * 25) * 4;
            int g = (row == 0) ? b : 512 + b * 3 + (row - 1);
            *(float4*)&FB[row * 100 + k4] = *(const float4*)&S0[(size_t)g * 100 + k4];
        }
        load_W(W, agg0_self + 5000, agg0_neigh + 5000, tid);
        __syncthreads();
        do_level(FB, SPEC + t * 100, M, W, 1, 1, 999, 999, 3, 0, 0, tid);       // -> v0
    }
    // random view (t-independent)
    for (int e = tid; e < 4 * 25; e += NTH) {
        int row = e / 25, k4 = (e - (e / 25) * 25) * 4;
        int g = (row == 0) ? b : 512 + b * 3 + (row - 1);
        *(float4*)&FB[row * 100 + k4] = *(const float4*)&rand_l0[(size_t)g * 100 + k4];
    }
    load_W(W, rand_self + 5000, rand_neigh + 5000, tid);
    __syncthreads();
    do_level(FB, SPEC + 4 * 100, M, W, 1, 1, 999, 999, 3, 0, 0, tid);           // -> v2,t0
    if (tid < 100) SPEC[5 * 100 + tid] = SPEC[4 * 100 + tid];                   // v2,t1
    __syncthreads();

    // ---------- attention + final ----------
    float* X   = SPEC;          // rows v*2+t
    float* LNX = FA;
    float* Q   = FA + 600;
    float* K   = FA + 1200;
    float* V   = FA + 1800;
    float* O   = FA + 2400;
    float* TMP = FA + 3000;
    float* mu  = FB;
    float* rs  = FB + 8;
    float* SC  = FB + 16;
    float* ATT = FB + 48;
    float* SEL = FB + 80;
    float* RES = FB + 192;
    float* part = FB + 400;

    mha_stage(X, LNX, Q, K, V, O, mu, rs, SC, ATT, 3, 2, vWq, vWk, vWv, vWf, vg, vb, tid);

    // reorder rows v*2+t -> t*3+v
    for (int e = tid; e < 600; e += NTH) TMP[e] = X[e];
    __syncthreads();
    for (int e = tid; e < 600; e += NTH) {
        int r = e / 100, d = e - r * 100;
        int t = r / 3, v = r - t * 3;
        X[e] = TMP[(v * 2 + t) * 100 + d];
    }
    __syncthreads();

    mha_stage(X, LNX, Q, K, V, O, mu, rs, SC, ATT, 2, 3, mWq, mWk, mWv, mWf, mg, mb, tid);

    const int typ = edgetype[BSZ + b];
    if (tid < 100) {
        SEL[tid] = (X[(typ * 3 + 0) * 100 + tid] +
                    X[(typ * 3 + 1) * 100 + tid] +
                    X[(typ * 3 + 2) * 100 + tid]) * (1.0f / 3.0f);
    }
    __syncthreads();

    const int node = nodeids[b];
    for (int o = tid; o < 200; o += NTH) {
        float acc = 0.f;
        const float* rp = reflect + (size_t)typ * 100 * 200 + o;
        for (int d = 0; d < 100; d++) acc += SEL[d] * rp[d * 200];
        RES[o] = base_embed[(size_t)node * 200 + o] + acc;
    }
    __syncthreads();
    float ps = 0.f;
    for (int o = tid; o < 200; o += NTH) ps += RES[o] * RES[o];
    part[tid] = ps;
    __syncthreads();
    if (tid == 0) {
        float s = 0.f;
        for (int i = 0; i < NTH; i++) s += part[i];
        part[0] = 1.0f / fmaxf(sqrtf(s), 1e-12f);
    }
    __syncthreads();
    float inv = part[0];
    for (int o = tid; o < 200; o += NTH) outp[(size_t)b * 200 + o] = RES[o] * inv;
}

// ---------------- host launcher ----------------
static void set_job(Job& j, const float* gsrc, float* out, const float* Ws, const float* Wn,
                    const int* neigh, int mode, int idx, int nseg,
                    const int* s, const int* fan, const int* noff,
                    int nb_b, int nb_t, int Rout, int Tj, int blk0) {
    j.gsrc = gsrc; j.out = out; j.Ws = Ws; j.Wn = Wn; j.neigh = neigh;
    j.mode = mode; j.idx = idx; j.nseg = nseg;
    for (int i = 0; i < 5; i++) j.s[i] = s[i];
    for (int i = 0; i < 4; i++) j.fan[i] = fan[i];
    for (int i = 0; i < 5; i++) j.noff[i] = noff[i];
    j.nb_b = nb_b; j.nb_t = nb_t; j.Rout = Rout; j.Rin = 0;
    j.rows = Rout * Tj; j.blk0 = blk0;
}

extern "C" void kernel_launch(void* const* d_in, const int* in_sizes, int n_in,
                              void* d_out, int out_size) {
    const int*   nodeids    = (const int*)d_in[0];
    const int*   edgetype   = (const int*)d_in[1];
    const int*   neighbors  = (const int*)d_in[2];
    const int*   rneigh     = (const int*)d_in[3];
    const float* base_embed = (const float*)d_in[4];
    const float* type_embed = (const float*)d_in[5];
    const float* rw_embed   = (const float*)d_in[6];
    const float* reflect    = (const float*)d_in[7];
    const float* agg0_self  = (const float*)d_in[8];
    const float* agg0_neigh = (const float*)d_in[9];
    const float* agg1_self  = (const float*)d_in[10];
    const float* agg1_neigh = (const float*)d_in[11];
    const float* rand_self  = (const float*)d_in[12];
    const float* rand_neighw= (const float*)d_in[13];
    const float* vWq = (const float*)d_in[14];
    const float* vWk = (const float*)d_in[15];
    const float* vWv = (const float*)d_in[16];
    const float* vWf = (const float*)d_in[17];
    const float* vg  = (const float*)d_in[18];
    const float* vb  = (const float*)d_in[19];
    const float* mWq = (const float*)d_in[20];
    const float* mWk = (const float*)d_in[21];
    const float* mWv = (const float*)d_in[22];
    const float* mWf = (const float*)d_in[23];
    const float* mg  = (const float*)d_in[24];
    const float* mb  = (const float*)d_in[25];
    float* outp = (float*)d_out;

    float* buf = nullptr;
    cudaGetSymbolAddress((void**)&buf, g_buf);

    cudaFuncSetAttribute(agg_multi_kernel,
                         cudaFuncAttributeMaxDynamicSharedMemorySize, AGG_SMEM_BYTES);
    cudaFuncSetAttribute(tail_kernel,
                         cudaFuncAttributeMaxDynamicSharedMemorySize, TK_SMEM_BYTES);

    const int s1[5]  = {1, 3, 15, 105, 945};
    const int f1[4]  = {3, 5, 7, 9};
    const int no1[5] = {0, 18, 21, 36, 141};
    const int s0[5]  = {1, 3, 15, 0, 0};
    const int f0[4]  = {3, 5, 0, 0};
    const int no0[5] = {0, 0, 3, 0, 0};

    MultiParams p;
    p.nodeids = nodeids;

    // ===== launch 1: all level-0 jobs =====
    {
        int b0 = 0;
        set_job(p.job[0], type_embed, buf + SCH1_L0, agg1_self, agg1_neigh, neighbors,
                1, 1, 4, s1, f1, no1, 2 * TOTAL_P, TOTAL_P, BSZ * 124, 2, b0);
        b0 += (p.job[0].rows + 63) / 64;
        set_job(p.job[1], type_embed, buf + SCH0_L0, agg0_self, agg0_neigh, neighbors,
                1, 0, 2, s0, f0, no0, 2 * TOTAL_P, TOTAL_P, BSZ * 4, 2, b0);
        b0 += (p.job[1].rows + 63) / 64;
        set_job(p.job[2], rw_embed, buf + RAND_L0, rand_self, rand_neighw, rneigh,
                2, 0, 2, s0, f0, no0, 18, 0, BSZ * 4, 1, b0);
        b0 += (p.job[2].rows + 63) / 64;
        p.njobs = 3;
        agg_multi_kernel<<<b0, 160, AGG_SMEM_BYTES>>>(p);
    }

    // ===== launch 2: fused tail (levels 1+ for all pipelines + attention + final) =====
    tail_kernel<<<BSZ, NTH, TK_SMEM_BYTES>>>(
        buf + SCH1_L0, buf + SCH0_L0, buf + RAND_L0,
        agg1_self, agg1_neigh, agg0_self, agg0_neigh, rand_self, rand_neighw,
        edgetype, nodeids, base_embed, reflect,
        vWq, vWk, vWv, vWf, vg, vb,
        mWq, mWk, mWv, mWf, mg, mb,
        outp);
}

// round 5
// speedup vs baseline: 1.7613x; 1.7613x over previous
#include <cuda_runtime.h>
#include <math.h>

// ---------------- problem constants ----------------
#define BSZ 512
#define DD 100
#define TOTAL_P 1086
#define NTH 256

// scratch buffer offsets (floats)
#define SCH1_L0 0ull            // [2][512*124][100]
#define SCH1_L1 12697600ull     // [2][512*19][100]
#define SCH0_L0 14643200ull     // [2][512*4][100]
#define SPEC0   15052800ull     // [2][512][100]
#define RAND_L0 15155200ull     // [512*4][100]
#define RVIEW   15360000ull     // [512][100]
#define SCRATCH_TOTAL 15411200ull

__device__ float g_buf[SCRATCH_TOTAL];

typedef unsigned long long ull;

__device__ __forceinline__ ull fma2(ull a, ull b, ull c) {
    ull d;
    asm("fma.rn.f32x2 %0, %1, %2, %3;" : "=l"(d) : "l"(a), "l"(b), "l"(c));
    return d;
}
__device__ __forceinline__ ull pack2(float a) {
    ull d;
    asm("mov.b64 %0, {%1, %1};" : "=l"(d) : "f"(a));
    return d;
}
__device__ __forceinline__ void unpack2(ull v, float& lo, float& hi) {
    asm("mov.b64 {%0, %1}, %2;" : "=f"(lo), "=f"(hi) : "l"(v));
}

// ================= GEMM-style aggregation kernel (L0 + L1 launches) =================
struct Job {
    const float* gsrc;
    float*       out;
    const float* Ws;
    const float* Wn;
    const int*   neigh;
    int mode;              // 0 = prev feats, 1 = type_embed, 2 = rw_embed
    int idx;
    int nseg;
    int s[5];
    int fan[4];
    int noff[5];
    int nb_b, nb_t;
    int Rout;
    int Rin;
    int rows;
    int blk0;
};
struct MultiParams {
    Job job[3];
    int njobs;
    const int* nodeids;
};

// shared layout (floats) — row-major A tiles, stride 100, sAm offset +16 for bank split
#define SM_AS   0
#define SM_AM   6416            // 6400 + 16 pad
#define SM_W    12816
#define SM_SELF 22816
#define SM_FAN  22880
#define SM_COFF 22944
#define SM_INVF 23520
#define SM_FLOATS 23584
#define AGG_SMEM_BYTES (SM_FLOATS * 4)

__global__ __launch_bounds__(160) void agg_multi_kernel(MultiParams p) {
    extern __shared__ float sm[];
    float* sAs  = sm + SM_AS;
    float* sAm  = sm + SM_AM;
    float* sW   = sm + SM_W;
    int*   sSelf = (int*)(sm + SM_SELF);
    int*   sFan  = (int*)(sm + SM_FAN);
    int*   sCoff = (int*)(sm + SM_COFF);
    float* sInvF = sm + SM_INVF;

    const int tid = threadIdx.x;

    int j = 0;
    if (p.njobs > 1 && (int)blockIdx.x >= p.job[1].blk0) j = 1;
    if (p.njobs > 2 && (int)blockIdx.x >= p.job[2].blk0) j = 2;
    Job jb = p.job[j];
    const int R0 = (blockIdx.x - jb.blk0) * 64;

    // ---- weights: [k][100] = [Ws | Wn] ----
    {
        const float* Ws = jb.Ws;
        const float* Wn = jb.Wn;
        for (int e = tid; e < 5000; e += 160) {
            int k = e / 50, pr = e - k * 50;
            int c = pr * 2;
            float2 v;
            if (c < 50) v = *(const float2*)(Ws + k * 50 + c);
            else        v = *(const float2*)(Wn + k * 50 + (c - 50));
            *(float2*)&sW[k * 100 + c] = v;
        }
    }

    // ---- per-row metadata ----
    if (tid < 64) {
        int R = R0 + tid;
        if (R >= jb.rows) R = jb.rows - 1;
        int t = (R >= jb.Rout) ? 1 : 0;
        int g = R - t * jb.Rout;
        int kk = 0, off = 0;
        while (kk + 1 < jb.nseg && g >= off + BSZ * jb.s[kk]) { off += BSZ * jb.s[kk]; kk++; }
        int local = g - off;
        int b = local / jb.s[kk];
        int i = local - b * jb.s[kk];
        int fan = jb.fan[kk];
        sFan[tid]  = fan;
        sInvF[tid] = 1.0f / (float)fan;
        int soff;
        if (jb.mode == 0) {
            soff = (t * jb.Rin + g) * DD;
        } else {
            int id = (kk == 0) ? p.nodeids[b]
                               : jb.neigh[b * jb.nb_b + t * jb.nb_t + jb.noff[kk] + i];
            soff = (jb.mode == 1) ? (id * 400 + t * 200 + jb.idx * 100) : id * DD;
        }
        sSelf[tid] = soff;
        if (jb.mode == 0) {
            int off2 = off + BSZ * jb.s[kk];
            int base = (t * jb.Rin + off2 + b * jb.s[kk + 1] + i * fan) * DD;
            for (int jj = 0; jj < fan; jj++) sCoff[tid * 9 + jj] = base + jj * DD;
        } else {
            int nb2 = b * jb.nb_b + t * jb.nb_t + jb.noff[kk + 1] + i * fan;
            for (int jj = 0; jj < fan; jj++) {
                int id = jb.neigh[nb2 + jj];
                sCoff[tid * 9 + jj] = (jb.mode == 1) ? (id * 400 + t * 200 + jb.idx * 100)
                                                     : id * DD;
            }
        }
    }
    __syncthreads();

    // ---- A tiles, row-major stride 100, float4 stores (conflict-free) ----
    const float* src = jb.gsrc;
    for (int e = tid; e < 1600; e += 160) {
        int row = e / 25, k4 = e - row * 25;
        float4 v = *(const float4*)(src + sSelf[row] + k4 * 4);
        *(float4*)&sAs[row * 100 + k4 * 4] = v;
    }
    for (int e = tid; e < 1600; e += 160) {
        int row = e / 25, k4 = e - row * 25;
        int f = sFan[row];
        const int* co = sCoff + row * 9;
        float x = 0.f, y = 0.f, z = 0.f, w = 0.f;
#pragma unroll
        for (int jj = 0; jj < 9; jj++) {
            if (jj < f) {
                float4 v = *(const float4*)(src + co[jj] + k4 * 4);
                x += v.x; y += v.y; z += v.z; w += v.w;
            }
        }
        float iv = sInvF[row];
        float4 r; r.x = x * iv; r.y = y * iv; r.z = z * iv; r.w = w * iv;
        *(float4*)&sAm[row * 100 + k4 * 4] = r;
    }
    __syncthreads();

    // ---- GEMM 64x100, K=100; thread = rows {rt, rt+16, rt+32, rt+48} x cols [10ct,10ct+10) ----
    const int ct = tid % 10, rt = tid / 10;
    const int c0 = ct * 10;
    const float* Ab = (ct < 5) ? sAs : sAm;
    const float* A0 = Ab + (rt +  0) * 100;
    const float* A1 = Ab + (rt + 16) * 100;
    const float* A2 = Ab + (rt + 32) * 100;
    const float* A3 = Ab + (rt + 48) * 100;

    ull acc[4][5];
#pragma unroll
    for (int r = 0; r < 4; r++)
#pragma unroll
        for (int q = 0; q < 5; q++) acc[r][q] = 0ull;

#pragma unroll 2
    for (int k = 0; k < 100; k++) {
        ull a0 = pack2(A0[k]);
        ull a1 = pack2(A1[k]);
        ull a2 = pack2(A2[k]);
        ull a3 = pack2(A3[k]);
        const ull* wp = (const ull*)&sW[k * 100 + c0];
        ull w0 = wp[0], w1 = wp[1], w2 = wp[2], w3 = wp[3], w4 = wp[4];
        acc[0][0] = fma2(a0, w0, acc[0][0]); acc[0][1] = fma2(a0, w1, acc[0][1]);
        acc[0][2] = fma2(a0, w2, acc[0][2]); acc[0][3] = fma2(a0, w3, acc[0][3]);
        acc[0][4] = fma2(a0, w4, acc[0][4]);
        acc[1][0] = fma2(a1, w0, acc[1][0]); acc[1][1] = fma2(a1, w1, acc[1][1]);
        acc[1][2] = fma2(a1, w2, acc[1][2]); acc[1][3] = fma2(a1, w3, acc[1][3]);
        acc[1][4] = fma2(a1, w4, acc[1][4]);
        acc[2][0] = fma2(a2, w0, acc[2][0]); acc[2][1] = fma2(a2, w1, acc[2][1]);
        acc[2][2] = fma2(a2, w2, acc[2][2]); acc[2][3] = fma2(a2, w3, acc[2][3]);
        acc[2][4] = fma2(a2, w4, acc[2][4]);
        acc[3][0] = fma2(a3, w0, acc[3][0]); acc[3][1] = fma2(a3, w1, acc[3][1]);
        acc[3][2] = fma2(a3, w2, acc[3][2]); acc[3][3] = fma2(a3, w3, acc[3][3]);
        acc[3][4] = fma2(a3, w4, acc[3][4]);
    }

#pragma unroll
    for (int r = 0; r < 4; r++) {
        int R = R0 + rt + 16 * r;
        if (R < jb.rows) {
            int t = (R >= jb.Rout) ? 1 : 0;
            int g = R - t * jb.Rout;
            float* op = jb.out + (size_t)(t * jb.Rout + g) * DD + c0;
#pragma unroll
            for (int q = 0; q < 5; q++) {
                float lo, hi;
                unpack2(acc[r][q], lo, hi);
                float2 o;
                o.x = fmaxf(lo, 0.f);
                o.y = fmaxf(hi, 0.f);
                *(float2*)(op + 2 * q) = o;
            }
        }
    }
}

// ================= fused small-tail kernel: sch1 L2+L3 + attention + final =================
// smem (floats)
#define TK_W    0
#define TK_F1   10000   // 19 rows
#define TK_F2   11900   // 4 rows
#define TK_M    12300   // 4 rows mean scratch
#define TK_SPEC 12800   // 6 rows (v*2+t)
#define TK_SCR  13400   // attn scratch 3000
#define TK_MISC 16400   // 600
#define TK_FLOATS 17000
#define TK_SMEM_BYTES (TK_FLOATS * 4)

__device__ __forceinline__ void load_W(float* W, const float* Ws, const float* Wn, int tid) {
    for (int e = tid; e < 5000; e += NTH) {
        int k = e / 50, c2 = (e - k * 50) * 2;
        float2 v;
        if (c2 < 50) v = *(const float2*)(Ws + k * 50 + c2);
        else         v = *(const float2*)(Wn + k * 50 + (c2 - 50));
        *(float2*)&W[k * 100 + c2] = v;
    }
}

__device__ __forceinline__ void do_level(
    const float* IN, float* OUT, float* M, const float* W,
    int nout, int O1, int O2, int O3, int F0, int F1, int F2, int tid)
{
    for (int it = tid; it < nout * 25; it += NTH) {
        int j = it / 25, k4 = (it - (it / 25) * 25) * 4;
        int k = (j >= O2) ? 2 : ((j >= O1) ? 1 : 0);
        int f  = (k == 0) ? F0 : (k == 1 ? F1 : F2);
        int o  = (k == 0) ? 0  : (k == 1 ? O1 : O2);
        int cs = (k == 0) ? O1 : (k == 1 ? O2 : O3);
        int cb = cs + (j - o) * f;
        float x = 0.f, y = 0.f, z = 0.f, w = 0.f;
        for (int i = 0; i < f; i++) {
            float4 v = *(const float4*)&IN[(cb + i) * 100 + k4];
            x += v.x; y += v.y; z += v.z; w += v.w;
        }
        float iv = 1.0f / (float)f;
        float4 r; r.x = x * iv; r.y = y * iv; r.z = z * iv; r.w = w * iv;
        *(float4*)&M[j * 100 + k4] = r;
    }
    __syncthreads();
    for (int it = tid; it < nout * 50; it += NTH) {
        int j = it / 50, cc = it - (it / 50) * 50;
        int h = cc / 25, c2 = cc - h * 25;
        int col = h * 50 + c2 * 2;
        const float* A = h ? (M + j * 100) : (IN + j * 100);
        ull acc = 0ull;
#pragma unroll 4
        for (int k = 0; k < 100; k++) {
            ull wv = *(const ull*)&W[k * 100 + col];
            acc = fma2(pack2(A[k]), wv, acc);
        }
        float lo, hi; unpack2(acc, lo, hi);
        OUT[j * 100 + col]     = fmaxf(lo, 0.f);
        OUT[j * 100 + col + 1] = fmaxf(hi, 0.f);
    }
    __syncthreads();
}

__device__ __forceinline__ void mha_stage(
    float* X, float* LNX, float* Q, float* K, float* V, float* O,
    float* mu, float* rs, float* SC, float* ATT,
    int nb, int na,
    const float* __restrict__ Wq, const float* __restrict__ Wk,
    const float* __restrict__ Wv, const float* __restrict__ Wf,
    const float* __restrict__ gam, const float* __restrict__ bet, int tid)
{
    if (tid < 6) {
        float s = 0.f;
        for (int d = 0; d < 100; d++) s += X[tid * 100 + d];
        float m = s * 0.01f;
        float v = 0.f;
        for (int d = 0; d < 100; d++) { float z = X[tid * 100 + d] - m; v += z * z; }
        mu[tid] = m;
        rs[tid] = rsqrtf(v * 0.01f + 1e-6f);
    }
    __syncthreads();
    for (int e = tid; e < 600; e += NTH) {
        int r = e / 100, d = e - r * 100;
        LNX[e] = (X[e] - mu[r]) * rs[r] * gam[d] + bet[d];
    }
    __syncthreads();
    if (tid < 100) {
        float aq[6], ak[6], av[6];
#pragma unroll
        for (int r = 0; r < 6; r++) { aq[r] = 0.f; ak[r] = 0.f; av[r] = 0.f; }
        for (int k2 = 0; k2 < 100; k2++) {
            float wq = Wq[k2 * 100 + tid];
            float wk = Wk[k2 * 100 + tid];
            float wv = Wv[k2 * 100 + tid];
#pragma unroll
            for (int r = 0; r < 6; r++) {
                aq[r] += LNX[r * 100 + k2] * wq;
                ak[r] += X[r * 100 + k2] * wk;
                av[r] += X[r * 100 + k2] * wv;
            }
        }
#pragma unroll
        for (int r = 0; r < 6; r++) {
            Q[r * 100 + tid] = aq[r];
            K[r * 100 + tid] = ak[r];
            V[r * 100 + tid] = av[r];
        }
    }
    __syncthreads();
    int nsc = nb * na * na;
    if (tid < nsc) {
        int bi = tid / (na * na), rem = tid - bi * na * na;
        int qa = rem / na, ka = rem - qa * na;
        const float* qp = Q + (bi * na + qa) * 100;
        const float* kp = K + (bi * na + ka) * 100;
        float s = 0.f;
        for (int d = 0; d < 100; d++) s += qp[d] * kp[d];
        SC[tid] = s * 0.1f;
    }
    __syncthreads();
    if (tid < nb * na) {
        int base = tid * na;
        float mx = -1e30f;
        for (int ka = 0; ka < na; ka++) mx = fmaxf(mx, SC[base + ka]);
        float ev[3], sum = 0.f;
        for (int ka = 0; ka < na; ka++) { ev[ka] = expf(SC[base + ka] - mx); sum += ev[ka]; }
        float inv = 1.0f / sum;
        for (int ka = 0; ka < na; ka++) ATT[base + ka] = ev[ka] * inv;
    }
    __syncthreads();
    if (tid < 100) {
        for (int bi = 0; bi < nb; bi++)
            for (int qa = 0; qa < na; qa++) {
                float acc = 0.f;
                for (int ka = 0; ka < na; ka++)
                    acc += ATT[(bi * na + qa) * na + ka] * V[(bi * na + ka) * 100 + tid];
                O[(bi * na + qa) * 100 + tid] = acc;
            }
    }
    __syncthreads();
    if (tid < 100) {
        float acc[6];
#pragma unroll
        for (int r = 0; r < 6; r++) acc[r] = 0.f;
        for (int k2 = 0; k2 < 100; k2++) {
            float wf = Wf[k2 * 100 + tid];
#pragma unroll
            for (int r = 0; r < 6; r++) acc[r] += O[r * 100 + k2] * wf;
        }
#pragma unroll
        for (int r = 0; r < 6; r++) X[r * 100 + tid] = acc[r] + X[r * 100 + tid];
    }
    __syncthreads();
}

__global__ __launch_bounds__(NTH) void tail_kernel(
    const float* __restrict__ sch1_l1,
    const float* __restrict__ spec0g, const float* __restrict__ rviewg,
    const float* __restrict__ agg1_self, const float* __restrict__ agg1_neigh,
    const int* __restrict__ edgetype, const int* __restrict__ nodeids,
    const float* __restrict__ base_embed, const float* __restrict__ reflect,
    const float* __restrict__ vWq, const float* __restrict__ vWk,
    const float* __restrict__ vWv, const float* __restrict__ vWf,
    const float* __restrict__ vg, const float* __restrict__ vb,
    const float* __restrict__ mWq, const float* __restrict__ mWk,
    const float* __restrict__ mWv, const float* __restrict__ mWf,
    const float* __restrict__ mg, const float* __restrict__ mb,
    float* __restrict__ outp)
{
    extern __shared__ float sm[];
    float* W    = sm + TK_W;
    float* F1   = sm + TK_F1;
    float* F2   = sm + TK_F2;
    float* M    = sm + TK_M;
    float* SPEC = sm + TK_SPEC;
    float* SCR  = sm + TK_SCR;
    float* MISC = sm + TK_MISC;

    const int b = blockIdx.x;
    const int tid = threadIdx.x;

    // ---------- schema1 L2 (19->4) + L3 (4->1) per t ----------
    for (int t = 0; t < 2; t++) {
        const float* L1 = sch1_l1 + (size_t)t * (512 * 19) * 100;
        for (int e = tid; e < 19 * 25; e += NTH) {
            int row = e / 25, k4 = (e - (e / 25) * 25) * 4;
            int g;
            if (row == 0)      g = b;
            else if (row < 4)  g = 512 + b * 3 + (row - 1);
            else               g = 2048 + b * 15 + (row - 4);
            *(float4*)&F1[row * 100 + k4] = *(const float4*)&L1[(size_t)g * 100 + k4];
        }
        load_W(W, agg1_self + 10000, agg1_neigh + 10000, tid);
        __syncthreads();
        do_level(F1, F2, M, W, 4, 1, 4, 19, 3, 5, 0, tid);
        load_W(W, agg1_self + 15000, agg1_neigh + 15000, tid);
        __syncthreads();
        do_level(F2, SPEC + (2 + t) * 100, M, W, 1, 1, 999, 999, 3, 0, 0, tid);
    }
    // spec0 (v=0) and rview (v=2)
    for (int e = tid; e < 200; e += NTH) {
        int t = e / 100, d = e - t * 100;
        SPEC[t * 100 + d] = spec0g[(size_t)(t * BSZ + b) * 100 + d];
    }
    for (int e = tid; e < 100; e += NTH) {
        float v = rviewg[(size_t)b * 100 + e];
        SPEC[4 * 100 + e] = v;
        SPEC[5 * 100 + e] = v;
    }
    __syncthreads();

    // ---------- attention + final ----------
    float* X   = SPEC;          // rows v*2+t
    float* LNX = SCR;
    float* Q   = SCR + 600;
    float* K   = SCR + 1200;
    float* V   = SCR + 1800;
    float* O   = SCR + 2400;
    float* TMP = F1;            // reuse F1 (1900 >= 600)
    float* mu  = MISC;
    float* rs  = MISC + 8;
    float* SC  = MISC + 16;
    float* ATT = MISC + 48;
    float* SEL = MISC + 80;
    float* RES = MISC + 192;
    float* part = MISC + 400;   // needs 128; MISC has 600 -> ok (400..527)

    mha_stage(X, LNX, Q, K, V, O, mu, rs, SC, ATT, 3, 2, vWq, vWk, vWv, vWf, vg, vb, tid);

    for (int e = tid; e < 600; e += NTH) TMP[e] = X[e];
    __syncthreads();
    for (int e = tid; e < 600; e += NTH) {
        int r = e / 100, d = e - r * 100;
        int t = r / 3, v = r - t * 3;
        X[e] = TMP[(v * 2 + t) * 100 + d];
    }
    __syncthreads();

    mha_stage(X, LNX, Q, K, V, O, mu, rs, SC, ATT, 2, 3, mWq, mWk, mWv, mWf, mg, mb, tid);

    const int typ = edgetype[BSZ + b];
    if (tid < 100) {
        SEL[tid] = (X[(typ * 3 + 0) * 100 + tid] +
                    X[(typ * 3 + 1) * 100 + tid] +
                    X[(typ * 3 + 2) * 100 + tid]) * (1.0f / 3.0f);
    }
    __syncthreads();

    const int node = nodeids[b];
    for (int o = tid; o < 200; o += NTH) {
        float acc = 0.f;
        const float* rp = reflect + (size_t)typ * 100 * 200 + o;
        for (int d = 0; d < 100; d++) acc += SEL[d] * rp[d * 200];
        RES[o] = base_embed[(size_t)node * 200 + o] + acc;
    }
    __syncthreads();
    float ps = 0.f;
    for (int o = tid; o < 200; o += NTH) ps += RES[o] * RES[o];
    part[tid % 128] = 0.f;
    __syncthreads();
    atomicAdd(&part[tid % 128], ps);
    __syncthreads();
    if (tid == 0) {
        float s = 0.f;
        for (int i = 0; i < 128; i++) s += part[i];
        part[0] = 1.0f / fmaxf(sqrtf(s), 1e-12f);
    }
    __syncthreads();
    float inv = part[0];
    for (int o = tid; o < 200; o += NTH) outp[(size_t)b * 200 + o] = RES[o] * inv;
}

// ---------------- host launcher ----------------
static void set_job(Job& j, const float* gsrc, float* out, const float* Ws, const float* Wn,
                    const int* neigh, int mode, int idx, int nseg,
                    const int* s, const int* fan, const int* noff,
                    int nb_b, int nb_t, int Rout, int Rin, int Tj, int blk0) {
    j.gsrc = gsrc; j.out = out; j.Ws = Ws; j.Wn = Wn; j.neigh = neigh;
    j.mode = mode; j.idx = idx; j.nseg = nseg;
    for (int i = 0; i < 5; i++) j.s[i] = s[i];
    for (int i = 0; i < 4; i++) j.fan[i] = fan[i];
    for (int i = 0; i < 5; i++) j.noff[i] = noff[i];
    j.nb_b = nb_b; j.nb_t = nb_t; j.Rout = Rout; j.Rin = Rin;
    j.rows = Rout * Tj; j.blk0 = blk0;
}

extern "C" void kernel_launch(void* const* d_in, const int* in_sizes, int n_in,
                              void* d_out, int out_size) {
    const int*   nodeids    = (const int*)d_in[0];
    const int*   edgetype   = (const int*)d_in[1];
    const int*   neighbors  = (const int*)d_in[2];
    const int*   rneigh     = (const int*)d_in[3];
    const float* base_embed = (const float*)d_in[4];
    const float* type_embed = (const float*)d_in[5];
    const float* rw_embed   = (const float*)d_in[6];
    const float* reflect    = (const float*)d_in[7];
    const float* agg0_self  = (const float*)d_in[8];
    const float* agg0_neigh = (const float*)d_in[9];
    const float* agg1_self  = (const float*)d_in[10];
    const float* agg1_neigh = (const float*)d_in[11];
    const float* rand_self  = (const float*)d_in[12];
    const float* rand_neighw= (const float*)d_in[13];
    const float* vWq = (const float*)d_in[14];
    const float* vWk = (const float*)d_in[15];
    const float* vWv = (const float*)d_in[16];
    const float* vWf = (const float*)d_in[17];
    const float* vg  = (const float*)d_in[18];
    const float* vb  = (const float*)d_in[19];
    const float* mWq = (const float*)d_in[20];
    const float* mWk = (const float*)d_in[21];
    const float* mWv = (const float*)d_in[22];
    const float* mWf = (const float*)d_in[23];
    const float* mg  = (const float*)d_in[24];
    const float* mb  = (const float*)d_in[25];
    float* outp = (float*)d_out;

    float* buf = nullptr;
    cudaGetSymbolAddress((void**)&buf, g_buf);

    cudaFuncSetAttribute(agg_multi_kernel,
                         cudaFuncAttributeMaxDynamicSharedMemorySize, AGG_SMEM_BYTES);
    cudaFuncSetAttribute(tail_kernel,
                         cudaFuncAttributeMaxDynamicSharedMemorySize, TK_SMEM_BYTES);

    const int s1[5]  = {1, 3, 15, 105, 945};
    const int f1[4]  = {3, 5, 7, 9};
    const int no1[5] = {0, 18, 21, 36, 141};
    const int s1b[5] = {1, 3, 15, 105, 0};
    const int f1b[4] = {3, 5, 7, 0};
    const int s0[5]  = {1, 3, 15, 0, 0};
    const int f0[4]  = {3, 5, 0, 0};
    const int no0[5] = {0, 0, 3, 0, 0};
    const int sT[5]  = {1, 3, 0, 0, 0};
    const int fT[4]  = {3, 0, 0, 0};
    const int noZ[5] = {0, 0, 0, 0, 0};

    MultiParams p;
    p.nodeids = nodeids;

    // ===== launch 1: all level-0 jobs =====
    {
        int b0 = 0;
        set_job(p.job[0], type_embed, buf + SCH1_L0, agg1_self, agg1_neigh, neighbors,
                1, 1, 4, s1, f1, no1, 2 * TOTAL_P, TOTAL_P, BSZ * 124, 0, 2, b0);
        b0 += (p.job[0].rows + 63) / 64;
        set_job(p.job[1], type_embed, buf + SCH0_L0, agg0_self, agg0_neigh, neighbors,
                1, 0, 2, s0, f0, no0, 2 * TOTAL_P, TOTAL_P, BSZ * 4, 0, 2, b0);
        b0 += (p.job[1].rows + 63) / 64;
        set_job(p.job[2], rw_embed, buf + RAND_L0, rand_self, rand_neighw, rneigh,
                2, 0, 2, s0, f0, no0, 18, 0, BSZ * 4, 0, 1, b0);
        b0 += (p.job[2].rows + 63) / 64;
        p.njobs = 3;
        agg_multi_kernel<<<b0, 160, AGG_SMEM_BYTES>>>(p);
    }
    // ===== launch 2: all level-1 jobs =====
    {
        int b0 = 0;
        set_job(p.job[0], buf + SCH1_L0, buf + SCH1_L1, agg1_self + 5000, agg1_neigh + 5000,
                nullptr, 0, 0, 3, s1b, f1b, noZ, 0, 0, BSZ * 19, BSZ * 124, 2, b0);
        b0 += (p.job[0].rows + 63) / 64;
        set_job(p.job[1], buf + SCH0_L0, buf + SPEC0, agg0_self + 5000, agg0_neigh + 5000,
                nullptr, 0, 0, 1, sT, fT, noZ, 0, 0, BSZ, BSZ * 4, 2, b0);
        b0 += (p.job[1].rows + 63) / 64;
        set_job(p.job[2], buf + RAND_L0, buf + RVIEW, rand_self + 5000, rand_neighw + 5000,
                nullptr, 0, 0, 1, sT, fT, noZ, 0, 0, BSZ, BSZ * 4, 1, b0);
        b0 += (p.job[2].rows + 63) / 64;
        p.njobs = 3;
        agg_multi_kernel<<<b0, 160, AGG_SMEM_BYTES>>>(p);
    }

    // ===== launch 3: fused tail (sch1 L2+L3 + attention + final) =====
    tail_kernel<<<BSZ, NTH, TK_SMEM_BYTES>>>(
        buf + SCH1_L1, buf + SPEC0, buf + RVIEW,
        agg1_self, agg1_neigh,
        edgetype, nodeids, base_embed, reflect,
        vWq, vWk, vWv, vWf, vg, vb,
        mWq, mWk, mWv, mWf, mg, mb,
        outp);
}

// round 7
// speedup vs baseline: 1.9544x; 1.1096x over previous
#include <cuda_runtime.h>
#include <math.h>

// ---------------- problem constants ----------------
#define BSZ 512
#define DD 100
#define TOTAL_P 1086
#define NTH 256

// scratch buffer offsets (floats)
#define SCH1_L0 0ull            // [2][512*124][100]
#define SCH1_L1 12697600ull     // [2][512*19][100]
#define SCH0_L0 14643200ull     // [2][512*4][100]
#define SPEC0   15052800ull     // [2][512][100]
#define RAND_L0 15155200ull     // [512*4][100]
#define RVIEW   15360000ull     // [512][100]
#define SCRATCH_TOTAL 15411200ull

__device__ float g_buf[SCRATCH_TOTAL];

typedef unsigned long long ull;

__device__ __forceinline__ ull fma2(ull a, ull b, ull c) {
    ull d;
    asm("fma.rn.f32x2 %0, %1, %2, %3;" : "=l"(d) : "l"(a), "l"(b), "l"(c));
    return d;
}
__device__ __forceinline__ ull pack2(float a) {
    ull d;
    asm("mov.b64 %0, {%1, %1};" : "=l"(d) : "f"(a));
    return d;
}
__device__ __forceinline__ void unpack2(ull v, float& lo, float& hi) {
    asm("mov.b64 {%0, %1}, %2;" : "=f"(lo), "=f"(hi) : "l"(v));
}

// ================= GEMM-style aggregation kernel (L0 + L1 launches) =================
// K-chunked (52 + 48) to cut smem to ~51KB -> 4 CTAs/SM for latency hiding.
struct Job {
    const float* gsrc;
    float*       out;
    const float* Ws;
    const float* Wn;
    const int*   neigh;
    int mode;              // 0 = prev feats, 1 = type_embed, 2 = rw_embed
    int idx;
    int nseg;
    int s[5];
    int fan[4];
    int noff[5];
    int nb_b, nb_t;
    int Rout;
    int Rin;
    int rows;
    int blk0;
};
struct MultiParams {
    Job job[3];
    int njobs;
    const int* nodeids;
};

// shared layout (floats): A tiles stride 52, +16-float offset between tiles
#define SM_AS   0               // [64*52] = 3328
#define SM_AM   3344            // 3328 + 16 pad
#define SM_W    6688            // [52*100] = 5200
#define SM_SELF 11888           // int[64]
#define SM_FAN  11952           // int[64]
#define SM_COFF 12016           // int[64*9]
#define SM_INVF 12592           // float[64]
#define SM_FLOATS 12656
#define AGG_SMEM_BYTES (SM_FLOATS * 4)

__global__ __launch_bounds__(160) void agg_multi_kernel(MultiParams p) {
    extern __shared__ float sm[];
    float* sAs  = sm + SM_AS;
    float* sAm  = sm + SM_AM;
    float* sW   = sm + SM_W;
    int*   sSelf = (int*)(sm + SM_SELF);
    int*   sFan  = (int*)(sm + SM_FAN);
    int*   sCoff = (int*)(sm + SM_COFF);
    float* sInvF = sm + SM_INVF;

    const int tid = threadIdx.x;

    int j = 0;
    if (p.njobs > 1 && (int)blockIdx.x >= p.job[1].blk0) j = 1;
    if (p.njobs > 2 && (int)blockIdx.x >= p.job[2].blk0) j = 2;
    Job jb = p.job[j];
    const int R0 = (blockIdx.x - jb.blk0) * 64;

    // ---- per-row metadata (once) ----
    if (tid < 64) {
        int R = R0 + tid;
        if (R >= jb.rows) R = jb.rows - 1;
        int t = (R >= jb.Rout) ? 1 : 0;
        int g = R - t * jb.Rout;
        int kk = 0, off = 0;
        while (kk + 1 < jb.nseg && g >= off + BSZ * jb.s[kk]) { off += BSZ * jb.s[kk]; kk++; }
        int local = g - off;
        int b = local / jb.s[kk];
        int i = local - b * jb.s[kk];
        int fan = jb.fan[kk];
        sFan[tid]  = fan;
        sInvF[tid] = 1.0f / (float)fan;
        int soff;
        if (jb.mode == 0) {
            soff = (t * jb.Rin + g) * DD;
        } else {
            int id = (kk == 0) ? p.nodeids[b]
                               : jb.neigh[b * jb.nb_b + t * jb.nb_t + jb.noff[kk] + i];
            soff = (jb.mode == 1) ? (id * 400 + t * 200 + jb.idx * 100) : id * DD;
        }
        sSelf[tid] = soff;
        if (jb.mode == 0) {
            int off2 = off + BSZ * jb.s[kk];
            int base = (t * jb.Rin + off2 + b * jb.s[kk + 1] + i * fan) * DD;
            for (int jj = 0; jj < fan; jj++) sCoff[tid * 9 + jj] = base + jj * DD;
        } else {
            int nb2 = b * jb.nb_b + t * jb.nb_t + jb.noff[kk + 1] + i * fan;
            for (int jj = 0; jj < fan; jj++) {
                int id = jb.neigh[nb2 + jj];
                sCoff[tid * 9 + jj] = (jb.mode == 1) ? (id * 400 + t * 200 + jb.idx * 100)
                                                     : id * DD;
            }
        }
    }

    // thread tile: rows {rt, rt+16, rt+32, rt+48}, cols [10ct, 10ct+10)
    const int ct = tid % 10, rt = tid / 10;
    const int c0 = ct * 10;

    ull acc[4][5];
#pragma unroll
    for (int r = 0; r < 4; r++)
#pragma unroll
        for (int q = 0; q < 5; q++) acc[r][q] = 0ull;

    const float* src = jb.gsrc;

    // ---- two K-chunks: [0,52) and [52,100) ----
#pragma unroll 1
    for (int c = 0; c < 2; c++) {
        const int k0  = (c == 0) ? 0 : 52;
        const int nk  = (c == 0) ? 52 : 48;
        const int nk4 = nk / 4;

        __syncthreads();   // covers metadata on first pass, prior-chunk reads later

        // stage W chunk [nk][100]
        {
            const float* Ws = jb.Ws;
            const float* Wn = jb.Wn;
            for (int e = tid; e < nk * 50; e += 160) {
                int k = e / 50, cc = (e - k * 50) * 2;
                float2 v;
                if (cc < 50) v = *(const float2*)(Ws + (k0 + k) * 50 + cc);
                else         v = *(const float2*)(Wn + (k0 + k) * 50 + (cc - 50));
                *(float2*)&sW[k * 100 + cc] = v;
            }
        }
        // stage A tiles (self + mean), float4 granularity
        for (int e = tid; e < 64 * nk4; e += 160) {
            int row = e / nk4, q = e - row * nk4;
            float4 v = *(const float4*)(src + sSelf[row] + k0 + 4 * q);
            *(float4*)&sAs[row * 52 + 4 * q] = v;
        }
        for (int e = tid; e < 64 * nk4; e += 160) {
            int row = e / nk4, q = e - row * nk4;
            int f = sFan[row];
            const int* co = sCoff + row * 9;
            float x = 0.f, y = 0.f, z = 0.f, w = 0.f;
#pragma unroll
            for (int jj = 0; jj < 9; jj++) {
                if (jj < f) {
                    float4 v = *(const float4*)(src + co[jj] + k0 + 4 * q);
                    x += v.x; y += v.y; z += v.z; w += v.w;
                }
            }
            float iv = sInvF[row];
            float4 r; r.x = x * iv; r.y = y * iv; r.z = z * iv; r.w = w * iv;
            *(float4*)&sAm[row * 52 + 4 * q] = r;
        }
        __syncthreads();

        const float* Ab = (ct < 5) ? sAs : sAm;
        const float* A0 = Ab + (rt +  0) * 52;
        const float* A1 = Ab + (rt + 16) * 52;
        const float* A2 = Ab + (rt + 32) * 52;
        const float* A3 = Ab + (rt + 48) * 52;

#pragma unroll 4
        for (int k = 0; k < nk; k++) {
            ull a0 = pack2(A0[k]);
            ull a1 = pack2(A1[k]);
            ull a2 = pack2(A2[k]);
            ull a3 = pack2(A3[k]);
            const ull* wp = (const ull*)&sW[k * 100 + c0];
            ull w0 = wp[0], w1 = wp[1], w2 = wp[2], w3 = wp[3], w4 = wp[4];
            acc[0][0] = fma2(a0, w0, acc[0][0]); acc[0][1] = fma2(a0, w1, acc[0][1]);
            acc[0][2] = fma2(a0, w2, acc[0][2]); acc[0][3] = fma2(a0, w3, acc[0][3]);
            acc[0][4] = fma2(a0, w4, acc[0][4]);
            acc[1][0] = fma2(a1, w0, acc[1][0]); acc[1][1] = fma2(a1, w1, acc[1][1]);
            acc[1][2] = fma2(a1, w2, acc[1][2]); acc[1][3] = fma2(a1, w3, acc[1][3]);
            acc[1][4] = fma2(a1, w4, acc[1][4]);
            acc[2][0] = fma2(a2, w0, acc[2][0]); acc[2][1] = fma2(a2, w1, acc[2][1]);
            acc[2][2] = fma2(a2, w2, acc[2][2]); acc[2][3] = fma2(a2, w3, acc[2][3]);
            acc[2][4] = fma2(a2, w4, acc[2][4]);
            acc[3][0] = fma2(a3, w0, acc[3][0]); acc[3][1] = fma2(a3, w1, acc[3][1]);
            acc[3][2] = fma2(a3, w2, acc[3][2]); acc[3][3] = fma2(a3, w3, acc[3][3]);
            acc[3][4] = fma2(a3, w4, acc[3][4]);
        }
    }

#pragma unroll
    for (int r = 0; r < 4; r++) {
        int R = R0 + rt + 16 * r;
        if (R < jb.rows) {
            int t = (R >= jb.Rout) ? 1 : 0;
            int g = R - t * jb.Rout;
            float* op = jb.out + (size_t)(t * jb.Rout + g) * DD + c0;
#pragma unroll
            for (int q = 0; q < 5; q++) {
                float lo, hi;
                unpack2(acc[r][q], lo, hi);
                float2 o;
                o.x = fmaxf(lo, 0.f);
                o.y = fmaxf(hi, 0.f);
                *(float2*)(op + 2 * q) = o;
            }
        }
    }
}

// ================= fused small-tail kernel: sch1 L2+L3 + attention + final =================
#define TK_W    0
#define TK_F1   10000
#define TK_F2   11900
#define TK_M    12300
#define TK_SPEC 12800
#define TK_SCR  13400
#define TK_MISC 16400
#define TK_FLOATS 17000
#define TK_SMEM_BYTES (TK_FLOATS * 4)

__device__ __forceinline__ void load_W(float* W, const float* Ws, const float* Wn, int tid) {
    for (int e = tid; e < 5000; e += NTH) {
        int k = e / 50, c2 = (e - k * 50) * 2;
        float2 v;
        if (c2 < 50) v = *(const float2*)(Ws + k * 50 + c2);
        else         v = *(const float2*)(Wn + k * 50 + (c2 - 50));
        *(float2*)&W[k * 100 + c2] = v;
    }
}

__device__ __forceinline__ void do_level(
    const float* IN, float* OUT, float* M, const float* W,
    int nout, int O1, int O2, int O3, int F0, int F1, int F2, int tid)
{
    for (int it = tid; it < nout * 25; it += NTH) {
        int j = it / 25, k4 = (it - (it / 25) * 25) * 4;
        int k = (j >= O2) ? 2 : ((j >= O1) ? 1 : 0);
        int f  = (k == 0) ? F0 : (k == 1 ? F1 : F2);
        int o  = (k == 0) ? 0  : (k == 1 ? O1 : O2);
        int cs = (k == 0) ? O1 : (k == 1 ? O2 : O3);
        int cb = cs + (j - o) * f;
        float x = 0.f, y = 0.f, z = 0.f, w = 0.f;
        for (int i = 0; i < f; i++) {
            float4 v = *(const float4*)&IN[(cb + i) * 100 + k4];
            x += v.x; y += v.y; z += v.z; w += v.w;
        }
        float iv = 1.0f / (float)f;
        float4 r; r.x = x * iv; r.y = y * iv; r.z = z * iv; r.w = w * iv;
        *(float4*)&M[j * 100 + k4] = r;
    }
    __syncthreads();
    for (int it = tid; it < nout * 50; it += NTH) {
        int j = it / 50, cc = it - (it / 50) * 50;
        int h = cc / 25, c2 = cc - h * 25;
        int col = h * 50 + c2 * 2;
        const float* A = h ? (M + j * 100) : (IN + j * 100);
        ull acc = 0ull;
#pragma unroll 4
        for (int k = 0; k < 100; k++) {
            ull wv = *(const ull*)&W[k * 100 + col];
            acc = fma2(pack2(A[k]), wv, acc);
        }
        float lo, hi; unpack2(acc, lo, hi);
        OUT[j * 100 + col]     = fmaxf(lo, 0.f);
        OUT[j * 100 + col + 1] = fmaxf(hi, 0.f);
    }
    __syncthreads();
}

__device__ __forceinline__ void mha_stage(
    float* X, float* LNX, float* Q, float* K, float* V, float* O,
    float* mu, float* rs, float* SC, float* ATT,
    int nb, int na,
    const float* __restrict__ Wq, const float* __restrict__ Wk,
    const float* __restrict__ Wv, const float* __restrict__ Wf,
    const float* __restrict__ gam, const float* __restrict__ bet, int tid)
{
    if (tid < 6) {
        float s = 0.f;
        for (int d = 0; d < 100; d++) s += X[tid * 100 + d];
        float m = s * 0.01f;
        float v = 0.f;
        for (int d = 0; d < 100; d++) { float z = X[tid * 100 + d] - m; v += z * z; }
        mu[tid] = m;
        rs[tid] = rsqrtf(v * 0.01f + 1e-6f);
    }
    __syncthreads();
    for (int e = tid; e < 600; e += NTH) {
        int r = e / 100, d = e - r * 100;
        LNX[e] = (X[e] - mu[r]) * rs[r] * gam[d] + bet[d];
    }
    __syncthreads();
    if (tid < 100) {
        float aq[6], ak[6], av[6];
#pragma unroll
        for (int r = 0; r < 6; r++) { aq[r] = 0.f; ak[r] = 0.f; av[r] = 0.f; }
        for (int k2 = 0; k2 < 100; k2++) {
            float wq = Wq[k2 * 100 + tid];
            float wk = Wk[k2 * 100 + tid];
            float wv = Wv[k2 * 100 + tid];
#pragma unroll
            for (int r = 0; r < 6; r++) {
                aq[r] += LNX[r * 100 + k2] * wq;
                ak[r] += X[r * 100 + k2] * wk;
                av[r] += X[r * 100 + k2] * wv;
            }
        }
#pragma unroll
        for (int r = 0; r < 6; r++) {
            Q[r * 100 + tid] = aq[r];
            K[r * 100 + tid] = ak[r];
            V[r * 100 + tid] = av[r];
        }
    }
    __syncthreads();
    int nsc = nb * na * na;
    if (tid < nsc) {
        int bi = tid / (na * na), rem = tid - bi * na * na;
        int qa = rem / na, ka = rem - qa * na;
        const float* qp = Q + (bi * na + qa) * 100;
        const float* kp = K + (bi * na + ka) * 100;
        float s = 0.f;
        for (int d = 0; d < 100; d++) s += qp[d] * kp[d];
        SC[tid] = s * 0.1f;
    }
    __syncthreads();
    if (tid < nb * na) {
        int base = tid * na;
        float mx = -1e30f;
        for (int ka = 0; ka < na; ka++) mx = fmaxf(mx, SC[base + ka]);
        float ev[3], sum = 0.f;
        for (int ka = 0; ka < na; ka++) { ev[ka] = expf(SC[base + ka] - mx); sum += ev[ka]; }
        float inv = 1.0f / sum;
        for (int ka = 0; ka < na; ka++) ATT[base + ka] = ev[ka] * inv;
    }
    __syncthreads();
    if (tid < 100) {
        for (int bi = 0; bi < nb; bi++)
            for (int qa = 0; qa < na; qa++) {
                float acc = 0.f;
                for (int ka = 0; ka < na; ka++)
                    acc += ATT[(bi * na + qa) * na + ka] * V[(bi * na + ka) * 100 + tid];
                O[(bi * na + qa) * 100 + tid] = acc;
            }
    }
    __syncthreads();
    if (tid < 100) {
        float acc[6];
#pragma unroll
        for (int r = 0; r < 6; r++) acc[r] = 0.f;
        for (int k2 = 0; k2 < 100; k2++) {
            float wf = Wf[k2 * 100 + tid];
#pragma unroll
            for (int r = 0; r < 6; r++) acc[r] += O[r * 100 + k2] * wf;
        }
#pragma unroll
        for (int r = 0; r < 6; r++) X[r * 100 + tid] = acc[r] + X[r * 100 + tid];
    }
    __syncthreads();
}

__global__ __launch_bounds__(NTH) void tail_kernel(
    const float* __restrict__ sch1_l1,
    const float* __restrict__ spec0g, const float* __restrict__ rviewg,
    const float* __restrict__ agg1_self, const float* __restrict__ agg1_neigh,
    const int* __restrict__ edgetype, const int* __restrict__ nodeids,
    const float* __restrict__ base_embed, const float* __restrict__ reflect,
    const float* __restrict__ vWq, const float* __restrict__ vWk,
    const float* __restrict__ vWv, const float* __restrict__ vWf,
    const float* __restrict__ vg, const float* __restrict__ vb,
    const float* __restrict__ mWq, const float* __restrict__ mWk,
    const float* __restrict__ mWv, const float* __restrict__ mWf,
    const float* __restrict__ mg, const float* __restrict__ mb,
    float* __restrict__ outp)
{
    extern __shared__ float sm[];
    float* W    = sm + TK_W;
    float* F1   = sm + TK_F1;
    float* F2   = sm + TK_F2;
    float* M    = sm + TK_M;
    float* SPEC = sm + TK_SPEC;
    float* SCR  = sm + TK_SCR;
    float* MISC = sm + TK_MISC;

    const int b = blockIdx.x;
    const int tid = threadIdx.x;

    for (int t = 0; t < 2; t++) {
        const float* L1 = sch1_l1 + (size_t)t * (512 * 19) * 100;
        for (int e = tid; e < 19 * 25; e += NTH) {
            int row = e / 25, k4 = (e - (e / 25) * 25) * 4;
            int g;
            if (row == 0)      g = b;
            else if (row < 4)  g = 512 + b * 3 + (row - 1);
            else               g = 2048 + b * 15 + (row - 4);
            *(float4*)&F1[row * 100 + k4] = *(const float4*)&L1[(size_t)g * 100 + k4];
        }
        load_W(W, agg1_self + 10000, agg1_neigh + 10000, tid);
        __syncthreads();
        do_level(F1, F2, M, W, 4, 1, 4, 19, 3, 5, 0, tid);
        load_W(W, agg1_self + 15000, agg1_neigh + 15000, tid);
        __syncthreads();
        do_level(F2, SPEC + (2 + t) * 100, M, W, 1, 1, 999, 999, 3, 0, 0, tid);
    }
    for (int e = tid; e < 200; e += NTH) {
        int t = e / 100, d = e - t * 100;
        SPEC[t * 100 + d] = spec0g[(size_t)(t * BSZ + b) * 100 + d];
    }
    for (int e = tid; e < 100; e += NTH) {
        float v = rviewg[(size_t)b * 100 + e];
        SPEC[4 * 100 + e] = v;
        SPEC[5 * 100 + e] = v;
    }
    __syncthreads();

    float* X   = SPEC;
    float* LNX = SCR;
    float* Q   = SCR + 600;
    float* K   = SCR + 1200;
    float* V   = SCR + 1800;
    float* O   = SCR + 2400;
    float* TMP = F1;
    float* mu  = MISC;
    float* rs  = MISC + 8;
    float* SC  = MISC + 16;
    float* ATT = MISC + 48;
    float* SEL = MISC + 80;
    float* RES = MISC + 192;
    float* part = MISC + 400;

    mha_stage(X, LNX, Q, K, V, O, mu, rs, SC, ATT, 3, 2, vWq, vWk, vWv, vWf, vg, vb, tid);

    for (int e = tid; e < 600; e += NTH) TMP[e] = X[e];
    __syncthreads();
    for (int e = tid; e < 600; e += NTH) {
        int r = e / 100, d = e - r * 100;
        int t = r / 3, v = r - t * 3;
        X[e] = TMP[(v * 2 + t) * 100 + d];
    }
    __syncthreads();

    mha_stage(X, LNX, Q, K, V, O, mu, rs, SC, ATT, 2, 3, mWq, mWk, mWv, mWf, mg, mb, tid);

    const int typ = edgetype[BSZ + b];
    if (tid < 100) {
        SEL[tid] = (X[(typ * 3 + 0) * 100 + tid] +
                    X[(typ * 3 + 1) * 100 + tid] +
                    X[(typ * 3 + 2) * 100 + tid]) * (1.0f / 3.0f);
    }
    __syncthreads();

    const int node = nodeids[b];
    for (int o = tid; o < 200; o += NTH) {
        float acc = 0.f;
        const float* rp = reflect + (size_t)typ * 100 * 200 + o;
        for (int d = 0; d < 100; d++) acc += SEL[d] * rp[d * 200];
        RES[o] = base_embed[(size_t)node * 200 + o] + acc;
    }
    __syncthreads();
    float ps = 0.f;
    for (int o = tid; o < 200; o += NTH) ps += RES[o] * RES[o];
    part[tid % 128] = 0.f;
    __syncthreads();
    atomicAdd(&part[tid % 128], ps);
    __syncthreads();
    if (tid == 0) {
        float s = 0.f;
        for (int i = 0; i < 128; i++) s += part[i];
        part[0] = 1.0f / fmaxf(sqrtf(s), 1e-12f);
    }
    __syncthreads();
    float inv = part[0];
    for (int o = tid; o < 200; o += NTH) outp[(size_t)b * 200 + o] = RES[o] * inv;
}

// ---------------- host launcher ----------------
static void set_job(Job& j, const float* gsrc, float* out, const float* Ws, const float* Wn,
                    const int* neigh, int mode, int idx, int nseg,
                    const int* s, const int* fan, const int* noff,
                    int nb_b, int nb_t, int Rout, int Rin, int Tj, int blk0) {
    j.gsrc = gsrc; j.out = out; j.Ws = Ws; j.Wn = Wn; j.neigh = neigh;
    j.mode = mode; j.idx = idx; j.nseg = nseg;
    for (int i = 0; i < 5; i++) j.s[i] = s[i];
    for (int i = 0; i < 4; i++) j.fan[i] = fan[i];
    for (int i = 0; i < 5; i++) j.noff[i] = noff[i];
    j.nb_b = nb_b; j.nb_t = nb_t; j.Rout = Rout; j.Rin = Rin;
    j.rows = Rout * Tj; j.blk0 = blk0;
}

extern "C" void kernel_launch(void* const* d_in, const int* in_sizes, int n_in,
                              void* d_out, int out_size) {
    const int*   nodeids    = (const int*)d_in[0];
    const int*   edgetype   = (const int*)d_in[1];
    const int*   neighbors  = (const int*)d_in[2];
    const int*   rneigh     = (const int*)d_in[3];
    const float* base_embed = (const float*)d_in[4];
    const float* type_embed = (const float*)d_in[5];
    const float* rw_embed   = (const float*)d_in[6];
    const float* reflect    = (const float*)d_in[7];
    const float* agg0_self  = (const float*)d_in[8];
    const float* agg0_neigh = (const float*)d_in[9];
    const float* agg1_self  = (const float*)d_in[10];
    const float* agg1_neigh = (const float*)d_in[11];
    const float* rand_self  = (const float*)d_in[12];
    const float* rand_neighw= (const float*)d_in[13];
    const float* vWq = (const float*)d_in[14];
    const float* vWk = (const float*)d_in[15];
    const float* vWv = (const float*)d_in[16];
    const float* vWf = (const float*)d_in[17];
    const float* vg  = (const float*)d_in[18];
    const float* vb  = (const float*)d_in[19];
    const float* mWq = (const float*)d_in[20];
    const float* mWk = (const float*)d_in[21];
    const float* mWv = (const float*)d_in[22];
    const float* mWf = (const float*)d_in[23];
    const float* mg  = (const float*)d_in[24];
    const float* mb  = (const float*)d_in[25];
    float* outp = (float*)d_out;

    float* buf = nullptr;
    cudaGetSymbolAddress((void**)&buf, g_buf);

    cudaFuncSetAttribute(agg_multi_kernel,
                         cudaFuncAttributeMaxDynamicSharedMemorySize, AGG_SMEM_BYTES);
    cudaFuncSetAttribute(tail_kernel,
                         cudaFuncAttributeMaxDynamicSharedMemorySize, TK_SMEM_BYTES);

    const int s1[5]  = {1, 3, 15, 105, 945};
    const int f1[4]  = {3, 5, 7, 9};
    const int no1[5] = {0, 18, 21, 36, 141};
    const int s1b[5] = {1, 3, 15, 105, 0};
    const int f1b[4] = {3, 5, 7, 0};
    const int s0[5]  = {1, 3, 15, 0, 0};
    const int f0[4]  = {3, 5, 0, 0};
    const int no0[5] = {0, 0, 3, 0, 0};
    const int sT[5]  = {1, 3, 0, 0, 0};
    const int fT[4]  = {3, 0, 0, 0};
    const int noZ[5] = {0, 0, 0, 0, 0};

    MultiParams p;
    p.nodeids = nodeids;

    // ===== launch 1: all level-0 jobs =====
    {
        int b0 = 0;
        set_job(p.job[0], type_embed, buf + SCH1_L0, agg1_self, agg1_neigh, neighbors,
                1, 1, 4, s1, f1, no1, 2 * TOTAL_P, TOTAL_P, BSZ * 124, 0, 2, b0);
        b0 += (p.job[0].rows + 63) / 64;
        set_job(p.job[1], type_embed, buf + SCH0_L0, agg0_self, agg0_neigh, neighbors,
                1, 0, 2, s0, f0, no0, 2 * TOTAL_P, TOTAL_P, BSZ * 4, 0, 2, b0);
        b0 += (p.job[1].rows + 63) / 64;
        set_job(p.job[2], rw_embed, buf + RAND_L0, rand_self, rand_neighw, rneigh,
                2, 0, 2, s0, f0, no0, 18, 0, BSZ * 4, 0, 1, b0);
        b0 += (p.job[2].rows + 63) / 64;
        p.njobs = 3;
        agg_multi_kernel<<<b0, 160, AGG_SMEM_BYTES>>>(p);
    }
    // ===== launch 2: all level-1 jobs =====
    {
        int b0 = 0;
        set_job(p.job[0], buf + SCH1_L0, buf + SCH1_L1, agg1_self + 5000, agg1_neigh + 5000,
                nullptr, 0, 0, 3, s1b, f1b, noZ, 0, 0, BSZ * 19, BSZ * 124, 2, b0);
        b0 += (p.job[0].rows + 63) / 64;
        set_job(p.job[1], buf + SCH0_L0, buf + SPEC0, agg0_self + 5000, agg0_neigh + 5000,
                nullptr, 0, 0, 1, sT, fT, noZ, 0, 0, BSZ, BSZ * 4, 2, b0);
        b0 += (p.job[1].rows + 63) / 64;
        set_job(p.job[2], buf + RAND_L0, buf + RVIEW, rand_self + 5000, rand_neighw + 5000,
                nullptr, 0, 0, 1, sT, fT, noZ, 0, 0, BSZ, BSZ * 4, 1, b0);
        b0 += (p.job[2].rows + 63) / 64;
        p.njobs = 3;
        agg_multi_kernel<<<b0, 160, AGG_SMEM_BYTES>>>(p);
    }

    // ===== launch 3: fused tail =====
    tail_kernel<<<BSZ, NTH, TK_SMEM_BYTES>>>(
        buf + SCH1_L1, buf + SPEC0, buf + RVIEW,
        agg1_self, agg1_neigh,
        edgetype, nodeids, base_embed, reflect,
        vWq, vWk, vWv, vWf, vg, vb,
        mWq, mWk, mWv, mWf, mg, mb,
        outp);
}

// round 8
// speedup vs baseline: 2.0636x; 1.0559x over previous
#include <cuda_runtime.h>
#include <math.h>

// ---------------- problem constants ----------------
#define BSZ 512
#define DD 100
#define TOTAL_P 1086
#define NTH 256

// scratch buffer offsets (floats)
#define SCH1_L0 0ull            // [2][512*124][100]
#define SCH1_L1 12697600ull     // [2][512*19][100]
#define SCH0_L0 14643200ull     // [2][512*4][100]
#define SPEC0   15052800ull     // [2][512][100]
#define RAND_L0 15155200ull     // [512*4][100]
#define RVIEW   15360000ull     // [512][100]
#define SCRATCH_TOTAL 15411200ull

__device__ float g_buf[SCRATCH_TOTAL];

typedef unsigned long long ull;

__device__ __forceinline__ ull fma2(ull a, ull b, ull c) {
    ull d;
    asm("fma.rn.f32x2 %0, %1, %2, %3;" : "=l"(d) : "l"(a), "l"(b), "l"(c));
    return d;
}
__device__ __forceinline__ ull pack2(float a) {
    ull d;
    asm("mov.b64 %0, {%1, %1};" : "=l"(d) : "f"(a));
    return d;
}
__device__ __forceinline__ void unpack2(ull v, float& lo, float& hi) {
    asm("mov.b64 {%0, %1}, %2;" : "=f"(lo), "=f"(hi) : "l"(v));
}

// ================= GEMM-style aggregation kernel (L0 + L1 launches) =================
// 3 K-chunks (36/32/32): smem ~36KB; launch_bounds(160,5) -> 25 warps/SM.
struct Job {
    const float* gsrc;
    float*       out;
    const float* Ws;
    const float* Wn;
    const int*   neigh;
    int mode;              // 0 = prev feats, 1 = type_embed, 2 = rw_embed
    int idx;
    int nseg;
    int s[5];
    int fan[4];
    int noff[5];
    int nb_b, nb_t;
    int Rout;
    int Rin;
    int rows;
    int blk0;
};
struct MultiParams {
    Job job[3];
    int njobs;
    const int* nodeids;
};

// shared layout (floats): A tiles stride 36
#define SM_AS   0               // [64*36] = 2304
#define SM_AM   2320            // 2304 + 16 pad
#define SM_W    4640            // [36*100] = 3600
#define SM_SELF 8240            // int[64]
#define SM_FAN  8304            // int[64]
#define SM_COFF 8368            // int[64*9]
#define SM_INVF 8944            // float[64]
#define SM_FLOATS 9008
#define AGG_SMEM_BYTES (SM_FLOATS * 4)

// 20 FFMA2 for one k-step: rows a0..a3 against w row (10 cols as 5 ull)
__device__ __forceinline__ void gstep(float a0, float a1, float a2, float a3,
                                      const float* wrow, ull acc[4][5]) {
    ull p0 = pack2(a0), p1 = pack2(a1), p2 = pack2(a2), p3 = pack2(a3);
    const ull* wp = (const ull*)wrow;
    ull w0 = wp[0], w1 = wp[1], w2 = wp[2], w3 = wp[3], w4 = wp[4];
    acc[0][0] = fma2(p0, w0, acc[0][0]); acc[0][1] = fma2(p0, w1, acc[0][1]);
    acc[0][2] = fma2(p0, w2, acc[0][2]); acc[0][3] = fma2(p0, w3, acc[0][3]);
    acc[0][4] = fma2(p0, w4, acc[0][4]);
    acc[1][0] = fma2(p1, w0, acc[1][0]); acc[1][1] = fma2(p1, w1, acc[1][1]);
    acc[1][2] = fma2(p1, w2, acc[1][2]); acc[1][3] = fma2(p1, w3, acc[1][3]);
    acc[1][4] = fma2(p1, w4, acc[1][4]);
    acc[2][0] = fma2(p2, w0, acc[2][0]); acc[2][1] = fma2(p2, w1, acc[2][1]);
    acc[2][2] = fma2(p2, w2, acc[2][2]); acc[2][3] = fma2(p2, w3, acc[2][3]);
    acc[2][4] = fma2(p2, w4, acc[2][4]);
    acc[3][0] = fma2(p3, w0, acc[3][0]); acc[3][1] = fma2(p3, w1, acc[3][1]);
    acc[3][2] = fma2(p3, w2, acc[3][2]); acc[3][3] = fma2(p3, w3, acc[3][3]);
    acc[3][4] = fma2(p3, w4, acc[3][4]);
}

__global__ __launch_bounds__(160, 5) void agg_multi_kernel(MultiParams p) {
    extern __shared__ float sm[];
    float* sAs  = sm + SM_AS;
    float* sAm  = sm + SM_AM;
    float* sW   = sm + SM_W;
    int*   sSelf = (int*)(sm + SM_SELF);
    int*   sFan  = (int*)(sm + SM_FAN);
    int*   sCoff = (int*)(sm + SM_COFF);
    float* sInvF = sm + SM_INVF;

    const int tid = threadIdx.x;

    int j = 0;
    if (p.njobs > 1 && (int)blockIdx.x >= p.job[1].blk0) j = 1;
    if (p.njobs > 2 && (int)blockIdx.x >= p.job[2].blk0) j = 2;
    Job jb = p.job[j];
    const int R0 = (blockIdx.x - jb.blk0) * 64;

    // ---- per-row metadata (once) ----
    if (tid < 64) {
        int R = R0 + tid;
        if (R >= jb.rows) R = jb.rows - 1;
        int t = (R >= jb.Rout) ? 1 : 0;
        int g = R - t * jb.Rout;
        int kk = 0, off = 0;
        while (kk + 1 < jb.nseg && g >= off + BSZ * jb.s[kk]) { off += BSZ * jb.s[kk]; kk++; }
        int local = g - off;
        int b = local / jb.s[kk];
        int i = local - b * jb.s[kk];
        int fan = jb.fan[kk];
        sFan[tid]  = fan;
        sInvF[tid] = 1.0f / (float)fan;
        int soff;
        if (jb.mode == 0) {
            soff = (t * jb.Rin + g) * DD;
        } else {
            int id = (kk == 0) ? p.nodeids[b]
                               : jb.neigh[b * jb.nb_b + t * jb.nb_t + jb.noff[kk] + i];
            soff = (jb.mode == 1) ? (id * 400 + t * 200 + jb.idx * 100) : id * DD;
        }
        sSelf[tid] = soff;
        if (jb.mode == 0) {
            int off2 = off + BSZ * jb.s[kk];
            int base = (t * jb.Rin + off2 + b * jb.s[kk + 1] + i * fan) * DD;
            for (int jj = 0; jj < fan; jj++) sCoff[tid * 9 + jj] = base + jj * DD;
        } else {
            int nb2 = b * jb.nb_b + t * jb.nb_t + jb.noff[kk + 1] + i * fan;
            for (int jj = 0; jj < fan; jj++) {
                int id = jb.neigh[nb2 + jj];
                sCoff[tid * 9 + jj] = (jb.mode == 1) ? (id * 400 + t * 200 + jb.idx * 100)
                                                     : id * DD;
            }
        }
    }

    // thread tile: rows {rt, rt+16, rt+32, rt+48}, cols [10ct, 10ct+10)
    const int ct = tid % 10, rt = tid / 10;
    const int c0 = ct * 10;

    ull acc[4][5];
#pragma unroll
    for (int r = 0; r < 4; r++)
#pragma unroll
        for (int q = 0; q < 5; q++) acc[r][q] = 0ull;

    const float* src = jb.gsrc;

    // ---- three K-chunks: [0,36), [36,68), [68,100) ----
#pragma unroll 1
    for (int c = 0; c < 3; c++) {
        const int k0  = (c == 0) ? 0 : (c == 1 ? 36 : 68);
        const int nk  = (c == 0) ? 36 : 32;
        const int nk4 = nk / 4;

        __syncthreads();   // covers metadata on first pass, prior-chunk reads later

        // stage W chunk [nk][100]
        {
            const float* Ws = jb.Ws;
            const float* Wn = jb.Wn;
            for (int e = tid; e < nk * 50; e += 160) {
                int k = e / 50, cc = (e - k * 50) * 2;
                float2 v;
                if (cc < 50) v = *(const float2*)(Ws + (k0 + k) * 50 + cc);
                else         v = *(const float2*)(Wn + (k0 + k) * 50 + (cc - 50));
                *(float2*)&sW[k * 100 + cc] = v;
            }
        }
        // stage A tiles (self + mean), float4 granularity
        for (int e = tid; e < 64 * nk4; e += 160) {
            int row = e / nk4, q = e - row * nk4;
            float4 v = *(const float4*)(src + sSelf[row] + k0 + 4 * q);
            *(float4*)&sAs[row * 36 + 4 * q] = v;
        }
        for (int e = tid; e < 64 * nk4; e += 160) {
            int row = e / nk4, q = e - row * nk4;
            int f = sFan[row];
            const int* co = sCoff + row * 9;
            float x = 0.f, y = 0.f, z = 0.f, w = 0.f;
#pragma unroll
            for (int jj = 0; jj < 9; jj++) {
                if (jj < f) {
                    float4 v = *(const float4*)(src + co[jj] + k0 + 4 * q);
                    x += v.x; y += v.y; z += v.z; w += v.w;
                }
            }
            float iv = sInvF[row];
            float4 r; r.x = x * iv; r.y = y * iv; r.z = z * iv; r.w = w * iv;
            *(float4*)&sAm[row * 36 + 4 * q] = r;
        }
        __syncthreads();

        const float* Ab = (ct < 5) ? sAs : sAm;
        const float* A0 = Ab + (rt +  0) * 36;
        const float* A1 = Ab + (rt + 16) * 36;
        const float* A2 = Ab + (rt + 32) * 36;
        const float* A3 = Ab + (rt + 48) * 36;

#pragma unroll 2
        for (int k = 0; k < nk; k += 4) {
            float4 a0 = *(const float4*)(A0 + k);
            float4 a1 = *(const float4*)(A1 + k);
            float4 a2 = *(const float4*)(A2 + k);
            float4 a3 = *(const float4*)(A3 + k);
            gstep(a0.x, a1.x, a2.x, a3.x, &sW[(k + 0) * 100 + c0], acc);
            gstep(a0.y, a1.y, a2.y, a3.y, &sW[(k + 1) * 100 + c0], acc);
            gstep(a0.z, a1.z, a2.z, a3.z, &sW[(k + 2) * 100 + c0], acc);
            gstep(a0.w, a1.w, a2.w, a3.w, &sW[(k + 3) * 100 + c0], acc);
        }
    }

#pragma unroll
    for (int r = 0; r < 4; r++) {
        int R = R0 + rt + 16 * r;
        if (R < jb.rows) {
            int t = (R >= jb.Rout) ? 1 : 0;
            int g = R - t * jb.Rout;
            float* op = jb.out + (size_t)(t * jb.Rout + g) * DD + c0;
#pragma unroll
            for (int q = 0; q < 5; q++) {
                float lo, hi;
                unpack2(acc[r][q], lo, hi);
                float2 o;
                o.x = fmaxf(lo, 0.f);
                o.y = fmaxf(hi, 0.f);
                *(float2*)(op + 2 * q) = o;
            }
        }
    }
}

// ================= fused small-tail kernel: sch1 L2+L3 + attention + final =================
#define TK_W    0
#define TK_F1   10000
#define TK_F2   11900
#define TK_M    12300
#define TK_SPEC 12800
#define TK_SCR  13400
#define TK_MISC 16400
#define TK_FLOATS 17000
#define TK_SMEM_BYTES (TK_FLOATS * 4)

__device__ __forceinline__ void load_W(float* W, const float* Ws, const float* Wn, int tid) {
    for (int e = tid; e < 5000; e += NTH) {
        int k = e / 50, c2 = (e - k * 50) * 2;
        float2 v;
        if (c2 < 50) v = *(const float2*)(Ws + k * 50 + c2);
        else         v = *(const float2*)(Wn + k * 50 + (c2 - 50));
        *(float2*)&W[k * 100 + c2] = v;
    }
}

__device__ __forceinline__ void do_level(
    const float* IN, float* OUT, float* M, const float* W,
    int nout, int O1, int O2, int O3, int F0, int F1, int F2, int tid)
{
    for (int it = tid; it < nout * 25; it += NTH) {
        int j = it / 25, k4 = (it - (it / 25) * 25) * 4;
        int k = (j >= O2) ? 2 : ((j >= O1) ? 1 : 0);
        int f  = (k == 0) ? F0 : (k == 1 ? F1 : F2);
        int o  = (k == 0) ? 0  : (k == 1 ? O1 : O2);
        int cs = (k == 0) ? O1 : (k == 1 ? O2 : O3);
        int cb = cs + (j - o) * f;
        float x = 0.f, y = 0.f, z = 0.f, w = 0.f;
        for (int i = 0; i < f; i++) {
            float4 v = *(const float4*)&IN[(cb + i) * 100 + k4];
            x += v.x; y += v.y; z += v.z; w += v.w;
        }
        float iv = 1.0f / (float)f;
        float4 r; r.x = x * iv; r.y = y * iv; r.z = z * iv; r.w = w * iv;
        *(float4*)&M[j * 100 + k4] = r;
    }
    __syncthreads();
    for (int it = tid; it < nout * 50; it += NTH) {
        int j = it / 50, cc = it - (it / 50) * 50;
        int h = cc / 25, c2 = cc - h * 25;
        int col = h * 50 + c2 * 2;
        const float* A = h ? (M + j * 100) : (IN + j * 100);
        ull acc = 0ull;
#pragma unroll 4
        for (int k = 0; k < 100; k++) {
            ull wv = *(const ull*)&W[k * 100 + col];
            acc = fma2(pack2(A[k]), wv, acc);
        }
        float lo, hi; unpack2(acc, lo, hi);
        OUT[j * 100 + col]     = fmaxf(lo, 0.f);
        OUT[j * 100 + col + 1] = fmaxf(hi, 0.f);
    }
    __syncthreads();
}

__device__ __forceinline__ void mha_stage(
    float* X, float* LNX, float* Q, float* K, float* V, float* O,
    float* mu, float* rs, float* SC, float* ATT,
    int nb, int na,
    const float* __restrict__ Wq, const float* __restrict__ Wk,
    const float* __restrict__ Wv, const float* __restrict__ Wf,
    const float* __restrict__ gam, const float* __restrict__ bet, int tid)
{
    if (tid < 6) {
        float s = 0.f;
        for (int d = 0; d < 100; d++) s += X[tid * 100 + d];
        float m = s * 0.01f;
        float v = 0.f;
        for (int d = 0; d < 100; d++) { float z = X[tid * 100 + d] - m; v += z * z; }
        mu[tid] = m;
        rs[tid] = rsqrtf(v * 0.01f + 1e-6f);
    }
    __syncthreads();
    for (int e = tid; e < 600; e += NTH) {
        int r = e / 100, d = e - r * 100;
        LNX[e] = (X[e] - mu[r]) * rs[r] * gam[d] + bet[d];
    }
    __syncthreads();
    if (tid < 100) {
        float aq[6], ak[6], av[6];
#pragma unroll
        for (int r = 0; r < 6; r++) { aq[r] = 0.f; ak[r] = 0.f; av[r] = 0.f; }
        for (int k2 = 0; k2 < 100; k2++) {
            float wq = Wq[k2 * 100 + tid];
            float wk = Wk[k2 * 100 + tid];
            float wv = Wv[k2 * 100 + tid];
#pragma unroll
            for (int r = 0; r < 6; r++) {
                aq[r] += LNX[r * 100 + k2] * wq;
                ak[r] += X[r * 100 + k2] * wk;
                av[r] += X[r * 100 + k2] * wv;
            }
        }
#pragma unroll
        for (int r = 0; r < 6; r++) {
            Q[r * 100 + tid] = aq[r];
            K[r * 100 + tid] = ak[r];
            V[r * 100 + tid] = av[r];
        }
    }
    __syncthreads();
    int nsc = nb * na * na;
    if (tid < nsc) {
        int bi = tid / (na * na), rem = tid - bi * na * na;
        int qa = rem / na, ka = rem - qa * na;
        const float* qp = Q + (bi * na + qa) * 100;
        const float* kp = K + (bi * na + ka) * 100;
        float s = 0.f;
        for (int d = 0; d < 100; d++) s += qp[d] * kp[d];
        SC[tid] = s * 0.1f;
    }
    __syncthreads();
    if (tid < nb * na) {
        int base = tid * na;
        float mx = -1e30f;
        for (int ka = 0; ka < na; ka++) mx = fmaxf(mx, SC[base + ka]);
        float ev[3], sum = 0.f;
        for (int ka = 0; ka < na; ka++) { ev[ka] = expf(SC[base + ka] - mx); sum += ev[ka]; }
        float inv = 1.0f / sum;
        for (int ka = 0; ka < na; ka++) ATT[base + ka] = ev[ka] * inv;
    }
    __syncthreads();
    if (tid < 100) {
        for (int bi = 0; bi < nb; bi++)
            for (int qa = 0; qa < na; qa++) {
                float acc = 0.f;
                for (int ka = 0; ka < na; ka++)
                    acc += ATT[(bi * na + qa) * na + ka] * V[(bi * na + ka) * 100 + tid];
                O[(bi * na + qa) * 100 + tid] = acc;
            }
    }
    __syncthreads();
    if (tid < 100) {
        float acc[6];
#pragma unroll
        for (int r = 0; r < 6; r++) acc[r] = 0.f;
        for (int k2 = 0; k2 < 100; k2++) {
            float wf = Wf[k2 * 100 + tid];
#pragma unroll
            for (int r = 0; r < 6; r++) acc[r] += O[r * 100 + k2] * wf;
        }
#pragma unroll
        for (int r = 0; r < 6; r++) X[r * 100 + tid] = acc[r] + X[r * 100 + tid];
    }
    __syncthreads();
}

__global__ __launch_bounds__(NTH) void tail_kernel(
    const float* __restrict__ sch1_l1,
    const float* __restrict__ spec0g, const float* __restrict__ rviewg,
    const float* __restrict__ agg1_self, const float* __restrict__ agg1_neigh,
    const int* __restrict__ edgetype, const int* __restrict__ nodeids,
    const float* __restrict__ base_embed, const float* __restrict__ reflect,
    const float* __restrict__ vWq, const float* __restrict__ vWk,
    const float* __restrict__ vWv, const float* __restrict__ vWf,
    const float* __restrict__ vg, const float* __restrict__ vb,
    const float* __restrict__ mWq, const float* __restrict__ mWk,
    const float* __restrict__ mWv, const float* __restrict__ mWf,
    const float* __restrict__ mg, const float* __restrict__ mb,
    float* __restrict__ outp)
{
    extern __shared__ float sm[];
    float* W    = sm + TK_W;
    float* F1   = sm + TK_F1;
    float* F2   = sm + TK_F2;
    float* M    = sm + TK_M;
    float* SPEC = sm + TK_SPEC;
    float* SCR  = sm + TK_SCR;
    float* MISC = sm + TK_MISC;

    const int b = blockIdx.x;
    const int tid = threadIdx.x;

    for (int t = 0; t < 2; t++) {
        const float* L1 = sch1_l1 + (size_t)t * (512 * 19) * 100;
        for (int e = tid; e < 19 * 25; e += NTH) {
            int row = e / 25, k4 = (e - (e / 25) * 25) * 4;
            int g;
            if (row == 0)      g = b;
            else if (row < 4)  g = 512 + b * 3 + (row - 1);
            else               g = 2048 + b * 15 + (row - 4);
            *(float4*)&F1[row * 100 + k4] = *(const float4*)&L1[(size_t)g * 100 + k4];
        }
        load_W(W, agg1_self + 10000, agg1_neigh + 10000, tid);
        __syncthreads();
        do_level(F1, F2, M, W, 4, 1, 4, 19, 3, 5, 0, tid);
        load_W(W, agg1_self + 15000, agg1_neigh + 15000, tid);
        __syncthreads();
        do_level(F2, SPEC + (2 + t) * 100, M, W, 1, 1, 999, 999, 3, 0, 0, tid);
    }
    for (int e = tid; e < 200; e += NTH) {
        int t = e / 100, d = e - t * 100;
        SPEC[t * 100 + d] = spec0g[(size_t)(t * BSZ + b) * 100 + d];
    }
    for (int e = tid; e < 100; e += NTH) {
        float v = rviewg[(size_t)b * 100 + e];
        SPEC[4 * 100 + e] = v;
        SPEC[5 * 100 + e] = v;
    }
    __syncthreads();

    float* X   = SPEC;
    float* LNX = SCR;
    float* Q   = SCR + 600;
    float* K   = SCR + 1200;
    float* V   = SCR + 1800;
    float* O   = SCR + 2400;
    float* TMP = F1;
    float* mu  = MISC;
    float* rs  = MISC + 8;
    float* SC  = MISC + 16;
    float* ATT = MISC + 48;
    float* SEL = MISC + 80;
    float* RES = MISC + 192;
    float* part = MISC + 400;

    mha_stage(X, LNX, Q, K, V, O, mu, rs, SC, ATT, 3, 2, vWq, vWk, vWv, vWf, vg, vb, tid);

    for (int e = tid; e < 600; e += NTH) TMP[e] = X[e];
    __syncthreads();
    for (int e = tid; e < 600; e += NTH) {
        int r = e / 100, d = e - r * 100;
        int t = r / 3, v = r - t * 3;
        X[e] = TMP[(v * 2 + t) * 100 + d];
    }
    __syncthreads();

    mha_stage(X, LNX, Q, K, V, O, mu, rs, SC, ATT, 2, 3, mWq, mWk, mWv, mWf, mg, mb, tid);

    const int typ = edgetype[BSZ + b];
    if (tid < 100) {
        SEL[tid] = (X[(typ * 3 + 0) * 100 + tid] +
                    X[(typ * 3 + 1) * 100 + tid] +
                    X[(typ * 3 + 2) * 100 + tid]) * (1.0f / 3.0f);
    }
    __syncthreads();

    const int node = nodeids[b];
    for (int o = tid; o < 200; o += NTH) {
        float acc = 0.f;
        const float* rp = reflect + (size_t)typ * 100 * 200 + o;
        for (int d = 0; d < 100; d++) acc += SEL[d] * rp[d * 200];
        RES[o] = base_embed[(size_t)node * 200 + o] + acc;
    }
    __syncthreads();
    float ps = 0.f;
    for (int o = tid; o < 200; o += NTH) ps += RES[o] * RES[o];
    part[tid % 128] = 0.f;
    __syncthreads();
    atomicAdd(&part[tid % 128], ps);
    __syncthreads();
    if (tid == 0) {
        float s = 0.f;
        for (int i = 0; i < 128; i++) s += part[i];
        part[0] = 1.0f / fmaxf(sqrtf(s), 1e-12f);
    }
    __syncthreads();
    float inv = part[0];
    for (int o = tid; o < 200; o += NTH) outp[(size_t)b * 200 + o] = RES[o] * inv;
}

// ---------------- host launcher ----------------
static void set_job(Job& j, const float* gsrc, float* out, const float* Ws, const float* Wn,
                    const int* neigh, int mode, int idx, int nseg,
                    const int* s, const int* fan, const int* noff,
                    int nb_b, int nb_t, int Rout, int Rin, int Tj, int blk0) {
    j.gsrc = gsrc; j.out = out; j.Ws = Ws; j.Wn = Wn; j.neigh = neigh;
    j.mode = mode; j.idx = idx; j.nseg = nseg;
    for (int i = 0; i < 5; i++) j.s[i] = s[i];
    for (int i = 0; i < 4; i++) j.fan[i] = fan[i];
    for (int i = 0; i < 5; i++) j.noff[i] = noff[i];
    j.nb_b = nb_b; j.nb_t = nb_t; j.Rout = Rout; j.Rin = Rin;
    j.rows = Rout * Tj; j.blk0 = blk0;
}

extern "C" void kernel_launch(void* const* d_in, const int* in_sizes, int n_in,
                              void* d_out, int out_size) {
    const int*   nodeids    = (const int*)d_in[0];
    const int*   edgetype   = (const int*)d_in[1];
    const int*   neighbors  = (const int*)d_in[2];
    const int*   rneigh     = (const int*)d_in[3];
    const float* base_embed = (const float*)d_in[4];
    const float* type_embed = (const float*)d_in[5];
    const float* rw_embed   = (const float*)d_in[6];
    const float* reflect    = (const float*)d_in[7];
    const float* agg0_self  = (const float*)d_in[8];
    const float* agg0_neigh = (const float*)d_in[9];
    const float* agg1_self  = (const float*)d_in[10];
    const float* agg1_neigh = (const float*)d_in[11];
    const float* rand_self  = (const float*)d_in[12];
    const float* rand_neighw= (const float*)d_in[13];
    const float* vWq = (const float*)d_in[14];
    const float* vWk = (const float*)d_in[15];
    const float* vWv = (const float*)d_in[16];
    const float* vWf = (const float*)d_in[17];
    const float* vg  = (const float*)d_in[18];
    const float* vb  = (const float*)d_in[19];
    const float* mWq = (const float*)d_in[20];
    const float* mWk = (const float*)d_in[21];
    const float* mWv = (const float*)d_in[22];
    const float* mWf = (const float*)d_in[23];
    const float* mg  = (const float*)d_in[24];
    const float* mb  = (const float*)d_in[25];
    float* outp = (float*)d_out;

    float* buf = nullptr;
    cudaGetSymbolAddress((void**)&buf, g_buf);

    cudaFuncSetAttribute(agg_multi_kernel,
                         cudaFuncAttributeMaxDynamicSharedMemorySize, AGG_SMEM_BYTES);
    cudaFuncSetAttribute(tail_kernel,
                         cudaFuncAttributeMaxDynamicSharedMemorySize, TK_SMEM_BYTES);

    const int s1[5]  = {1, 3, 15, 105, 945};
    const int f1[4]  = {3, 5, 7, 9};
    const int no1[5] = {0, 18, 21, 36, 141};
    const int s1b[5] = {1, 3, 15, 105, 0};
    const int f1b[4] = {3, 5, 7, 0};
    const int s0[5]  = {1, 3, 15, 0, 0};
    const int f0[4]  = {3, 5, 0, 0};
    const int no0[5] = {0, 0, 3, 0, 0};
    const int sT[5]  = {1, 3, 0, 0, 0};
    const int fT[4]  = {3, 0, 0, 0};
    const int noZ[5] = {0, 0, 0, 0, 0};

    MultiParams p;
    p.nodeids = nodeids;

    // ===== launch 1: all level-0 jobs =====
    {
        int b0 = 0;
        set_job(p.job[0], type_embed, buf + SCH1_L0, agg1_self, agg1_neigh, neighbors,
                1, 1, 4, s1, f1, no1, 2 * TOTAL_P, TOTAL_P, BSZ * 124, 0, 2, b0);
        b0 += (p.job[0].rows + 63) / 64;
        set_job(p.job[1], type_embed, buf + SCH0_L0, agg0_self, agg0_neigh, neighbors,
                1, 0, 2, s0, f0, no0, 2 * TOTAL_P, TOTAL_P, BSZ * 4, 0, 2, b0);
        b0 += (p.job[1].rows + 63) / 64;
        set_job(p.job[2], rw_embed, buf + RAND_L0, rand_self, rand_neighw, rneigh,
                2, 0, 2, s0, f0, no0, 18, 0, BSZ * 4, 0, 1, b0);
        b0 += (p.job[2].rows + 63) / 64;
        p.njobs = 3;
        agg_multi_kernel<<<b0, 160, AGG_SMEM_BYTES>>>(p);
    }
    // ===== launch 2: all level-1 jobs =====
    {
        int b0 = 0;
        set_job(p.job[0], buf + SCH1_L0, buf + SCH1_L1, agg1_self + 5000, agg1_neigh + 5000,
                nullptr, 0, 0, 3, s1b, f1b, noZ, 0, 0, BSZ * 19, BSZ * 124, 2, b0);
        b0 += (p.job[0].rows + 63) / 64;
        set_job(p.job[1], buf + SCH0_L0, buf + SPEC0, agg0_self + 5000, agg0_neigh + 5000,
                nullptr, 0, 0, 1, sT, fT, noZ, 0, 0, BSZ, BSZ * 4, 2, b0);
        b0 += (p.job[1].rows + 63) / 64;
        set_job(p.job[2], buf + RAND_L0, buf + RVIEW, rand_self + 5000, rand_neighw + 5000,
                nullptr, 0, 0, 1, sT, fT, noZ, 0, 0, BSZ, BSZ * 4, 1, b0);
        b0 += (p.job[2].rows + 63) / 64;
        p.njobs = 3;
        agg_multi_kernel<<<b0, 160, AGG_SMEM_BYTES>>>(p);
    }

    // ===== launch 3: fused tail =====
    tail_kernel<<<BSZ, NTH, TK_SMEM_BYTES>>>(
        buf + SCH1_L1, buf + SPEC0, buf + RVIEW,
        agg1_self, agg1_neigh,
        edgetype, nodeids, base_embed, reflect,
        vWq, vWk, vWv, vWf, vg, vb,
        mWq, mWk, mWv, mWf, mg, mb,
        outp);
}